// round 2
// baseline (speedup 1.0000x reference)
#include <cuda_runtime.h>
#include <math.h>

#define BATCH 1024
#define FEAT  2048
#define NCLS  11003
#define CT    86        // ceil(11003/128)

// ---------------- scratch (static device globals; no allocation) ------------
__device__ float g_vn[BATCH * FEAT];          // normalized visual rows
__device__ float g_tn[BATCH * FEAT];          // normalized textual rows
__device__ float g_invwn[11008];              // 1/||W[:,j]||
__device__ float g_partial[2 * BATCH * CT];   // per (mod,row,classTile) sumexp
__device__ float g_lab[2 * BATCH];            // label logit per (mod,row)
__device__ float g_simpart[64];               // per-block sim loss partials
__device__ int   g_lab32;                     // 1 if labels buffer is int32

// ---------------- helpers ---------------------------------------------------
__device__ __forceinline__ float blockReduceSum(float v, float* sm) {
    int tid = threadIdx.x;
    sm[tid] = v;
    __syncthreads();
    for (int s = blockDim.x >> 1; s > 0; s >>= 1) {
        if (tid < s) sm[tid] += sm[tid + s];
        __syncthreads();
    }
    float r = sm[0];
    __syncthreads();
    return r;
}

__device__ __forceinline__ int get_label(const void* labels, int i) {
    if (g_lab32) return ((const int*)labels)[i];
    return (int)(((const long long*)labels)[i]);
}

__device__ __forceinline__ float softplusf(float x) {
    return fmaxf(x, 0.f) + log1pf(__expf(-fabsf(x)));
}

// ---------------- label dtype detection -------------------------------------
__global__ void detect_labels_kernel(const void* labels) {
    // If buffer is really int32, viewing as int64 combines pairs -> values
    // >= NCLS (or negative) with overwhelming probability over 16 samples.
    if (threadIdx.x == 0 && blockIdx.x == 0) {
        const long long* p = (const long long*)labels;
        int is32 = 0;
        for (int i = 0; i < 16; i++) {
            long long v = p[i];
            if (v < 0 || v >= (long long)NCLS) { is32 = 1; break; }
        }
        g_lab32 = is32;
    }
}

// ---------------- row L2 normalize ------------------------------------------
__global__ void prep_kernel(const float* __restrict__ v,
                            const float* __restrict__ t) {
    __shared__ float sm[256];
    int b = blockIdx.x;
    int mod = b >> 10;
    int row = b & 1023;
    const float* src = (mod ? t : v) + (size_t)row * FEAT;
    float* dst = (mod ? g_tn : g_vn) + (size_t)row * FEAT;
    float s = 0.f;
    for (int k = threadIdx.x; k < FEAT; k += 256) {
        float x = src[k];
        s += x * x;
    }
    s = blockReduceSum(s, sm);
    float inv = rsqrtf(s);
    for (int k = threadIdx.x; k < FEAT; k += 256) dst[k] = src[k] * inv;
}

// ---------------- W column inverse norms ------------------------------------
__global__ void wnorm_kernel(const float* __restrict__ W) {
    int j = blockIdx.x * blockDim.x + threadIdx.x;
    if (j >= NCLS) return;
    const float* p = W + j;
    float s0 = 0.f, s1 = 0.f, s2 = 0.f, s3 = 0.f;
    #pragma unroll 2
    for (int k = 0; k < FEAT; k += 8) {
        float x0 = p[(size_t)(k + 0) * NCLS];
        float x1 = p[(size_t)(k + 1) * NCLS];
        float x2 = p[(size_t)(k + 2) * NCLS];
        float x3 = p[(size_t)(k + 3) * NCLS];
        float x4 = p[(size_t)(k + 4) * NCLS];
        float x5 = p[(size_t)(k + 5) * NCLS];
        float x6 = p[(size_t)(k + 6) * NCLS];
        float x7 = p[(size_t)(k + 7) * NCLS];
        s0 = fmaf(x0, x0, s0); s1 = fmaf(x1, x1, s1);
        s2 = fmaf(x2, x2, s2); s3 = fmaf(x3, x3, s3);
        s0 = fmaf(x4, x4, s0); s1 = fmaf(x5, x5, s1);
        s2 = fmaf(x6, x6, s2); s3 = fmaf(x7, x7, s3);
    }
    g_invwn[j] = rsqrtf((s0 + s1) + (s2 + s3));
}

// ---------------- main GEMM + fused exp-sum epilogue ------------------------
// grid: (CT, 8, 2)  block: 256.  Tile 128x128, K-step 8, 8x8 per thread.
__global__ __launch_bounds__(256, 2)
void gemm_sumexp_kernel(const float* __restrict__ W) {
    __shared__ float As[8][128];
    __shared__ float Bs[8][128];
    __shared__ float red[128][17];

    int tid = threadIdx.x;
    int tx = tid & 15, ty = tid >> 4;
    int colBase = blockIdx.x * 128;
    int rowBase = blockIdx.y * 128;
    const float* A = blockIdx.z ? g_tn : g_vn;

    float acc[8][8];
    #pragma unroll
    for (int i = 0; i < 8; i++)
        #pragma unroll
        for (int j = 0; j < 8; j++) acc[i][j] = 0.f;

    int aRow = tid >> 1;
    int aK = (tid & 1) * 4;
    int bK = tid >> 5;
    int bCol = tid & 31;
    const float* Aptr = A + (size_t)(rowBase + aRow) * FEAT + aK;

    for (int k0 = 0; k0 < FEAT; k0 += 8) {
        float4 av = *(const float4*)(Aptr + k0);
        As[aK + 0][aRow] = av.x;
        As[aK + 1][aRow] = av.y;
        As[aK + 2][aRow] = av.z;
        As[aK + 3][aRow] = av.w;
        const float* wrow = W + (size_t)(k0 + bK) * NCLS + colBase + bCol;
        #pragma unroll
        for (int u = 0; u < 4; u++) {
            int c = colBase + bCol + u * 32;
            Bs[bK][bCol + u * 32] = (c < NCLS) ? wrow[u * 32] : 0.f;
        }
        __syncthreads();
        #pragma unroll
        for (int kk = 0; kk < 8; kk++) {
            float a[8], b[8];
            float4 t0 = *(const float4*)&As[kk][ty * 4];
            float4 t1 = *(const float4*)&As[kk][64 + ty * 4];
            a[0] = t0.x; a[1] = t0.y; a[2] = t0.z; a[3] = t0.w;
            a[4] = t1.x; a[5] = t1.y; a[6] = t1.z; a[7] = t1.w;
            float4 u0 = *(const float4*)&Bs[kk][tx * 4];
            float4 u1 = *(const float4*)&Bs[kk][64 + tx * 4];
            b[0] = u0.x; b[1] = u0.y; b[2] = u0.z; b[3] = u0.w;
            b[4] = u1.x; b[5] = u1.y; b[6] = u1.z; b[7] = u1.w;
            #pragma unroll
            for (int i = 0; i < 8; i++)
                #pragma unroll
                for (int j = 0; j < 8; j++)
                    acc[i][j] = fmaf(a[i], b[j], acc[i][j]);
        }
        __syncthreads();
    }

    // epilogue: logit = 28 * acc * invwn[col];  sumexp(logit - 28) per row
    float rowsum[8];
    #pragma unroll
    for (int i = 0; i < 8; i++) {
        rowsum[i] = 0.f;
        #pragma unroll
        for (int j = 0; j < 8; j++) {
            int c = colBase + (j & 3) + ((j >> 2) * 64) + tx * 4;
            if (c < NCLS) {
                float logit = 28.f * acc[i][j] * g_invwn[c];
                rowsum[i] += __expf(logit - 28.f);
            }
        }
    }
    #pragma unroll
    for (int i = 0; i < 8; i++) {
        int m = (i & 3) + ((i >> 2) * 64) + ty * 4;
        red[m][tx] = rowsum[i];
    }
    __syncthreads();
    if (tid < 128) {
        float s = 0.f;
        #pragma unroll
        for (int x = 0; x < 16; x++) s += red[tid][x];
        int grow = blockIdx.z * BATCH + rowBase + tid;
        g_partial[(size_t)grow * CT + blockIdx.x] = s;
    }
}

// ---------------- label logits ----------------------------------------------
__global__ void lab_kernel(const float* __restrict__ W, const void* labels) {
    __shared__ float sm[256];
    int b = blockIdx.x;
    int mod = b >> 10;
    int row = b & 1023;
    const float* e = (mod ? g_tn : g_vn) + (size_t)row * FEAT;
    int lab = get_label(labels, row);
    float s = 0.f;
    for (int k = threadIdx.x; k < FEAT; k += 256)
        s = fmaf(e[k], W[(size_t)k * NCLS + lab], s);
    s = blockReduceSum(s, sm);
    if (threadIdx.x == 0) g_lab[b] = 28.f * s * g_invwn[lab];
}

// ---------------- sim = v @ t^T with fused masked softplus ------------------
// grid: (8, 8)  block: 256.  Same 128x128 tiling.
__global__ __launch_bounds__(256, 2)
void sim_kernel(const void* labels) {
    __shared__ float As[8][128];
    __shared__ float Bs[8][128];
    __shared__ float sm[256];

    int tid = threadIdx.x;
    int tx = tid & 15, ty = tid >> 4;
    int rowBase = blockIdx.y * 128;
    int colBase = blockIdx.x * 128;

    float acc[8][8];
    #pragma unroll
    for (int i = 0; i < 8; i++)
        #pragma unroll
        for (int j = 0; j < 8; j++) acc[i][j] = 0.f;

    int lRow = tid >> 1;
    int lK = (tid & 1) * 4;
    const float* Ap = g_vn + (size_t)(rowBase + lRow) * FEAT + lK;
    const float* Bp = g_tn + (size_t)(colBase + lRow) * FEAT + lK;

    for (int k0 = 0; k0 < FEAT; k0 += 8) {
        float4 av = *(const float4*)(Ap + k0);
        As[lK + 0][lRow] = av.x;
        As[lK + 1][lRow] = av.y;
        As[lK + 2][lRow] = av.z;
        As[lK + 3][lRow] = av.w;
        float4 bv = *(const float4*)(Bp + k0);
        Bs[lK + 0][lRow] = bv.x;
        Bs[lK + 1][lRow] = bv.y;
        Bs[lK + 2][lRow] = bv.z;
        Bs[lK + 3][lRow] = bv.w;
        __syncthreads();
        #pragma unroll
        for (int kk = 0; kk < 8; kk++) {
            float a[8], b[8];
            float4 t0 = *(const float4*)&As[kk][ty * 4];
            float4 t1 = *(const float4*)&As[kk][64 + ty * 4];
            a[0] = t0.x; a[1] = t0.y; a[2] = t0.z; a[3] = t0.w;
            a[4] = t1.x; a[5] = t1.y; a[6] = t1.z; a[7] = t1.w;
            float4 u0 = *(const float4*)&Bs[kk][tx * 4];
            float4 u1 = *(const float4*)&Bs[kk][64 + tx * 4];
            b[0] = u0.x; b[1] = u0.y; b[2] = u0.z; b[3] = u0.w;
            b[4] = u1.x; b[5] = u1.y; b[6] = u1.z; b[7] = u1.w;
            #pragma unroll
            for (int i = 0; i < 8; i++)
                #pragma unroll
                for (int j = 0; j < 8; j++)
                    acc[i][j] = fmaf(a[i], b[j], acc[i][j]);
        }
        __syncthreads();
    }

    int lr[8], lc[8];
    #pragma unroll
    for (int i = 0; i < 8; i++)
        lr[i] = get_label(labels, rowBase + (i & 3) + ((i >> 2) * 64) + ty * 4);
    #pragma unroll
    for (int j = 0; j < 8; j++)
        lc[j] = get_label(labels, colBase + (j & 3) + ((j >> 2) * 64) + tx * 4);

    float s = 0.f;
    #pragma unroll
    for (int i = 0; i < 8; i++)
        #pragma unroll
        for (int j = 0; j < 8; j++) {
            float x = acc[i][j];
            float val;
            if (lr[i] == lc[j]) val = softplusf(-10.f * (x - 0.6f));
            else                val = softplusf( 40.f * (x - 0.4f));
            s += val;
        }
    s = blockReduceSum(s, sm);
    if (tid == 0) g_simpart[blockIdx.y * 8 + blockIdx.x] = s;
}

// ---------------- finalize ---------------------------------------------------
__global__ void finalize_kernel(float* __restrict__ out) {
    __shared__ float sm[256];
    int tid = threadIdx.x;
    float ce = 0.f;
    for (int r = tid; r < 2 * BATCH; r += 256) {
        float s = 0.f;
        const float* p = &g_partial[(size_t)r * CT];
        for (int c = 0; c < CT; c++) s += p[c];
        ce += 28.f + logf(s) - g_lab[r];
    }
    ce = blockReduceSum(ce, sm);
    float simv = (tid < 64) ? g_simpart[tid] : 0.f;
    simv = blockReduceSum(simv, sm);
    if (tid == 0) {
        out[0] = ce / (float)BATCH;                 // instance loss
        out[1] = 2.f * simv / (float)BATCH;         // global align loss
    }
}

// ---------------- launch -----------------------------------------------------
extern "C" void kernel_launch(void* const* d_in, const int* in_sizes, int n_in,
                              void* d_out, int out_size) {
    const float* v = (const float*)d_in[0];
    const float* t = (const float*)d_in[1];
    const void*  labels = d_in[2];
    const float* W = (const float*)d_in[3];
    float* out = (float*)d_out;

    detect_labels_kernel<<<1, 32>>>(labels);
    prep_kernel<<<2 * BATCH, 256>>>(v, t);
    wnorm_kernel<<<(NCLS + 255) / 256, 256>>>(W);
    dim3 gg(CT, BATCH / 128, 2);
    gemm_sumexp_kernel<<<gg, 256>>>(W);
    lab_kernel<<<2 * BATCH, 256>>>(W, labels);
    dim3 gs(BATCH / 128, BATCH / 128, 1);
    sim_kernel<<<gs, 256>>>(labels);
    finalize_kernel<<<1, 256>>>(out);
}

// round 11
// speedup vs baseline: 2.7126x; 2.7126x over previous
#include <cuda_runtime.h>
#include <math.h>
#include <stdint.h>

#define BATCH 1024
#define FEAT  2048
#define NCLS  11003
#define NCLSP 11008
#define CT    43            // ceil(11003/256)
#define BM 128
#define BN 256
#define BK 32
#define LDP 36              // padded smem row pitch in floats
#define A_FLOATS (BM*LDP)   // 4608
#define B_FLOATS (BN*LDP)   // 9216
#define SMEM_FLOATS (2*A_FLOATS + 2*B_FLOATS)   // 27648
#define SMEM_ALLOC (SMEM_FLOATS*4)              // 110592 B

// ---------------- scratch -----------------------------------------------------
__device__ float g_emb[2 * BATCH * FEAT];      // tf32-rounded normalized v,t rows
__device__ float g_Wt[(size_t)NCLSP * FEAT];   // tf32-rounded W^T * invwn (padded 0)
__device__ float g_invwn[NCLSP];
__device__ float g_partial[2 * BATCH * CT];
__device__ float g_lab[2 * BATCH];
__device__ float g_simpart[32];
__device__ int   g_lab32;

// ---------------- helpers ------------------------------------------------------
static __device__ __forceinline__ uint32_t smem_u32(const void* p) {
    uint32_t a;
    asm("{ .reg .u64 t; cvta.to.shared.u64 t, %1; cvt.u32.u64 %0, t; }"
        : "=r"(a) : "l"(p));
    return a;
}
static __device__ __forceinline__ void cp16(uint32_t dst, const float* src) {
    asm volatile("cp.async.cg.shared.global [%0], [%1], 16;"
                 :: "r"(dst), "l"(src) : "memory");
}
static __device__ __forceinline__ float to_tf32(float x) {
    float r;
    asm("cvt.rna.tf32.f32 %0, %1;" : "=f"(r) : "f"(x));
    return r;
}
__device__ __forceinline__ float blockReduceSum(float v, float* sm) {
    int tid = threadIdx.x;
    sm[tid] = v;
    __syncthreads();
    for (int s = blockDim.x >> 1; s > 0; s >>= 1) {
        if (tid < s) sm[tid] += sm[tid + s];
        __syncthreads();
    }
    float r = sm[0];
    __syncthreads();
    return r;
}
__device__ __forceinline__ int get_label(const void* labels, int i) {
    if (g_lab32) return ((const int*)labels)[i];
    return (int)(((const long long*)labels)[i]);
}
__device__ __forceinline__ float softplusf(float x) {
    return fmaxf(x, 0.f) + log1pf(__expf(-fabsf(x)));
}

#define MMA_OP(d, a0, a1, a2, a3, b0, b1) \
    asm volatile("mma.sync.aligned.m16n8k8.row.col.f32.tf32.tf32.f32 " \
                 "{%0,%1,%2,%3}, {%4,%5,%6,%7}, {%8,%9}, {%0,%1,%2,%3};" \
                 : "+f"(d[0]), "+f"(d[1]), "+f"(d[2]), "+f"(d[3]) \
                 : "r"(a0), "r"(a1), "r"(a2), "r"(a3), "r"(b0), "r"(b1))

// C[128x256] += A[128x2048] @ B[256x2048]^T, both K-major tf32-rounded fp32.
// 8 warps (2m x 4n), warp tile 64x64, cp.async double-buffered BK=32.
#define GEMM_MAINLOOP(Ag, Bg, acc, smf)                                          \
  do {                                                                           \
    const int tid_ = threadIdx.x;                                                \
    const int wid_ = tid_ >> 5, lane_ = tid_ & 31;                               \
    const int wm_ = (wid_ >> 2) * 64, wn_ = (wid_ & 3) * 64;                     \
    const int lq_ = lane_ >> 2, lk_ = lane_ & 3;                                 \
    uint32_t sb_ = smem_u32(smf);                                                \
    int aSm_[4], aG_[4], bSm_[8], bG_[8];                                        \
    _Pragma("unroll") for (int i = 0; i < 4; i++) {                              \
      int f = tid_ + i * 256, r = f >> 3, c = f & 7;                             \
      aSm_[i] = (r * LDP + c * 4) * 4; aG_[i] = r * FEAT + c * 4; }              \
    _Pragma("unroll") for (int i = 0; i < 8; i++) {                              \
      int f = tid_ + i * 256, r = f >> 3, c = f & 7;                             \
      bSm_[i] = (r * LDP + c * 4) * 4; bG_[i] = r * FEAT + c * 4; }              \
    uint32_t aB_[2] = { sb_, sb_ + A_FLOATS * 4u };                              \
    uint32_t bB_[2] = { sb_ + 2u * A_FLOATS * 4u,                                \
                        sb_ + 2u * A_FLOATS * 4u + B_FLOATS * 4u };              \
    _Pragma("unroll") for (int i = 0; i < 4; i++) cp16(aB_[0] + aSm_[i], (Ag) + aG_[i]); \
    _Pragma("unroll") for (int i = 0; i < 8; i++) cp16(bB_[0] + bSm_[i], (Bg) + bG_[i]); \
    asm volatile("cp.async.commit_group;" ::: "memory");                         \
    for (int s = 0; s < FEAT / BK; s++) {                                        \
      if (s + 1 < FEAT / BK) {                                                   \
        int k0 = (s + 1) * BK, st = (s + 1) & 1;                                 \
        _Pragma("unroll") for (int i = 0; i < 4; i++)                            \
          cp16(aB_[st] + aSm_[i], (Ag) + aG_[i] + k0);                           \
        _Pragma("unroll") for (int i = 0; i < 8; i++)                            \
          cp16(bB_[st] + bSm_[i], (Bg) + bG_[i] + k0);                           \
      }                                                                          \
      asm volatile("cp.async.commit_group;" ::: "memory");                       \
      asm volatile("cp.async.wait_group 1;" ::: "memory");                       \
      __syncthreads();                                                           \
      const uint32_t* Asm_ = (const uint32_t*)((smf) + (s & 1) * A_FLOATS);      \
      const uint32_t* Bsm_ = (const uint32_t*)((smf) + 2 * A_FLOATS + (s & 1) * B_FLOATS); \
      _Pragma("unroll") for (int kk = 0; kk < 4; kk++) {                         \
        uint32_t af_[4][4];                                                      \
        _Pragma("unroll") for (int mf = 0; mf < 4; mf++) {                       \
          int base = (wm_ + mf * 16 + lq_) * LDP + kk * 8 + lk_;                 \
          af_[mf][0] = Asm_[base];            af_[mf][1] = Asm_[base + 8 * LDP]; \
          af_[mf][2] = Asm_[base + 4];        af_[mf][3] = Asm_[base + 8 * LDP + 4]; } \
        _Pragma("unroll") for (int nf = 0; nf < 8; nf++) {                       \
          int base = (wn_ + nf * 8 + lq_) * LDP + kk * 8 + lk_;                  \
          uint32_t b0_ = Bsm_[base], b1_ = Bsm_[base + 4];                       \
          _Pragma("unroll") for (int mf = 0; mf < 4; mf++)                       \
            MMA_OP(acc[mf][nf], af_[mf][0], af_[mf][1], af_[mf][2], af_[mf][3], b0_, b1_); \
        }                                                                        \
      }                                                                          \
      __syncthreads();                                                           \
    }                                                                            \
    asm volatile("cp.async.wait_group 0;" ::: "memory");                         \
    __syncthreads();                                                             \
  } while (0)

// ---------------- label dtype detection ---------------------------------------
__global__ void detect_labels_kernel(const void* labels) {
    if (threadIdx.x == 0 && blockIdx.x == 0) {
        const long long* p = (const long long*)labels;
        int is32 = 0;
        for (int i = 0; i < 16; i++) {
            long long v = p[i];
            if (v < 0 || v >= (long long)NCLS) { is32 = 1; break; }
        }
        g_lab32 = is32;
    }
}

// ---------------- row L2 normalize (tf32-rounded) into g_emb --------------------
__global__ void prep_kernel(const float* __restrict__ v, const float* __restrict__ t) {
    __shared__ float sm[256];
    int b = blockIdx.x;
    const float* src = (b >= BATCH) ? t + (size_t)(b - BATCH) * FEAT
                                    : v + (size_t)b * FEAT;
    float* dst = g_emb + (size_t)b * FEAT;
    float s = 0.f;
    for (int k = threadIdx.x; k < FEAT; k += 256) { float x = src[k]; s += x * x; }
    s = blockReduceSum(s, sm);
    float inv = rsqrtf(s);
    for (int k = threadIdx.x; k < FEAT; k += 256) dst[k] = to_tf32(src[k] * inv);
}

// ---------------- W column inverse norms ---------------------------------------
__global__ void wnorm_kernel(const float* __restrict__ W) {
    int j = blockIdx.x * blockDim.x + threadIdx.x;
    if (j >= NCLS) return;
    const float* p = W + j;
    float s0 = 0.f, s1 = 0.f, s2 = 0.f, s3 = 0.f;
    #pragma unroll 2
    for (int k = 0; k < FEAT; k += 4) {
        float x0 = p[(size_t)(k + 0) * NCLS];
        float x1 = p[(size_t)(k + 1) * NCLS];
        float x2 = p[(size_t)(k + 2) * NCLS];
        float x3 = p[(size_t)(k + 3) * NCLS];
        s0 = fmaf(x0, x0, s0); s1 = fmaf(x1, x1, s1);
        s2 = fmaf(x2, x2, s2); s3 = fmaf(x3, x3, s3);
    }
    g_invwn[j] = rsqrtf((s0 + s1) + (s2 + s3));
}

// ---------------- transpose + normalize (tf32-rounded) into g_Wt ----------------
__global__ void transpose_kernel(const float* __restrict__ W) {
    __shared__ float tile[32][33];
    int n = blockIdx.x * 32 + threadIdx.x;
    int k0 = blockIdx.y * 32;
    #pragma unroll
    for (int kk = 0; kk < 4; kk++) {
        int k = k0 + threadIdx.y + kk * 8;
        float val = 0.f;
        if (n < NCLS) val = to_tf32(W[(size_t)k * NCLS + n] * g_invwn[n]);
        tile[threadIdx.y + kk * 8][threadIdx.x] = val;
    }
    __syncthreads();
    #pragma unroll
    for (int kk = 0; kk < 4; kk++) {
        int nl = threadIdx.y + kk * 8;
        g_Wt[(size_t)(blockIdx.x * 32 + nl) * FEAT + k0 + threadIdx.x] = tile[threadIdx.x][nl];
    }
}

// ---------------- main GEMM (mma.sync tf32) + fused sumexp epilogue -------------
__global__ __launch_bounds__(256, 1) void gemm_main() {
    extern __shared__ float smf[];
    int colBase = blockIdx.x * BN;
    int rowBase = blockIdx.y * BM;
    const float* Ag = g_emb + (size_t)rowBase * FEAT;
    const float* Bg = g_Wt + (size_t)colBase * FEAT;

    float acc[4][8][4];
    #pragma unroll
    for (int m = 0; m < 4; m++)
        #pragma unroll
        for (int n = 0; n < 8; n++)
            #pragma unroll
            for (int q = 0; q < 4; q++) acc[m][n][q] = 0.f;

    GEMM_MAINLOOP(Ag, Bg, acc, smf);

    int tid = threadIdx.x;
    int wid = tid >> 5, lane = tid & 31;
    int wm = (wid >> 2) * 64, wn = (wid & 3) * 64;
    int lq = lane >> 2, lk = lane & 3;

    float rs[4][2];
    #pragma unroll
    for (int mf = 0; mf < 4; mf++) { rs[mf][0] = 0.f; rs[mf][1] = 0.f; }
    #pragma unroll
    for (int mf = 0; mf < 4; mf++)
        #pragma unroll
        for (int nf = 0; nf < 8; nf++) {
            int c = colBase + wn + nf * 8 + 2 * lk;
            float e0 = (c     < NCLS) ? __expf(fmaf(28.f, acc[mf][nf][0], -28.f)) : 0.f;
            float e1 = (c + 1 < NCLS) ? __expf(fmaf(28.f, acc[mf][nf][1], -28.f)) : 0.f;
            float e2 = (c     < NCLS) ? __expf(fmaf(28.f, acc[mf][nf][2], -28.f)) : 0.f;
            float e3 = (c + 1 < NCLS) ? __expf(fmaf(28.f, acc[mf][nf][3], -28.f)) : 0.f;
            rs[mf][0] += e0 + e1;
            rs[mf][1] += e2 + e3;
        }
    #pragma unroll
    for (int mf = 0; mf < 4; mf++)
        #pragma unroll
        for (int h = 0; h < 2; h++) {
            rs[mf][h] += __shfl_xor_sync(0xffffffffu, rs[mf][h], 1);
            rs[mf][h] += __shfl_xor_sync(0xffffffffu, rs[mf][h], 2);
        }
    float* red = smf;  // 512 floats
    if (lk == 0) {
        #pragma unroll
        for (int mf = 0; mf < 4; mf++)
            #pragma unroll
            for (int h = 0; h < 2; h++)
                red[(wm + mf * 16 + lq + 8 * h) * 4 + (wid & 3)] = rs[mf][h];
    }
    __syncthreads();
    if (tid < 128) {
        float s = red[tid * 4] + red[tid * 4 + 1] + red[tid * 4 + 2] + red[tid * 4 + 3];
        g_partial[(size_t)(rowBase + tid) * CT + blockIdx.x] = s;
    }
}

// ---------------- sim GEMM (mma.sync tf32) + fused masked softplus --------------
__global__ __launch_bounds__(256, 1) void sim_main(const void* labels) {
    extern __shared__ float smf[];
    int colBase = blockIdx.x * BN;   // textual index
    int rowBase = blockIdx.y * BM;   // visual index
    const float* Ag = g_emb + (size_t)rowBase * FEAT;
    const float* Bg = g_emb + (size_t)(BATCH + colBase) * FEAT;

    float acc[4][8][4];
    #pragma unroll
    for (int m = 0; m < 4; m++)
        #pragma unroll
        for (int n = 0; n < 8; n++)
            #pragma unroll
            for (int q = 0; q < 4; q++) acc[m][n][q] = 0.f;

    GEMM_MAINLOOP(Ag, Bg, acc, smf);

    int tid = threadIdx.x;
    int wid = tid >> 5, lane = tid & 31;
    int wm = (wid >> 2) * 64, wn = (wid & 3) * 64;
    int lq = lane >> 2, lk = lane & 3;

    int* scol = (int*)(smf + 1024);
    int* srow = (int*)(smf + 1024 + 256);
    scol[tid] = get_label(labels, colBase + tid);
    if (tid < 128) srow[tid] = get_label(labels, rowBase + tid);
    __syncthreads();

    float s = 0.f;
    #pragma unroll
    for (int mf = 0; mf < 4; mf++) {
        int r0 = wm + mf * 16 + lq;
        int la = srow[r0], lb = srow[r0 + 8];
        #pragma unroll
        for (int nf = 0; nf < 8; nf++) {
            int c = wn + nf * 8 + 2 * lk;
            int lc0 = scol[c], lc1 = scol[c + 1];
            float x0 = acc[mf][nf][0], x1 = acc[mf][nf][1];
            float x2 = acc[mf][nf][2], x3 = acc[mf][nf][3];
            s += softplusf((la == lc0) ? (-10.f * (x0 - 0.6f)) : (40.f * (x0 - 0.4f)));
            s += softplusf((la == lc1) ? (-10.f * (x1 - 0.6f)) : (40.f * (x1 - 0.4f)));
            s += softplusf((lb == lc0) ? (-10.f * (x2 - 0.6f)) : (40.f * (x2 - 0.4f)));
            s += softplusf((lb == lc1) ? (-10.f * (x3 - 0.6f)) : (40.f * (x3 - 0.4f)));
        }
    }
    __syncthreads();
    s = blockReduceSum(s, smf);
    if (tid == 0) g_simpart[blockIdx.y * 4 + blockIdx.x] = s;
}

// ---------------- label logits --------------------------------------------------
__global__ void lab_kernel(const void* labels) {
    __shared__ float sm[256];
    int b = blockIdx.x;  // 0..2047
    const float* e = g_emb + (size_t)b * FEAT;
    int lab = get_label(labels, b & (BATCH - 1));
    const float* w = g_Wt + (size_t)lab * FEAT;
    float s = 0.f;
    for (int k = threadIdx.x; k < FEAT; k += 256) s = fmaf(e[k], w[k], s);
    s = blockReduceSum(s, sm);
    if (threadIdx.x == 0) g_lab[b] = 28.f * s;   // invwn folded into g_Wt
}

// ---------------- finalize ------------------------------------------------------
__global__ void finalize_kernel(float* __restrict__ out) {
    __shared__ float sm[256];
    int tid = threadIdx.x;
    float ce = 0.f;
    for (int r = tid; r < 2 * BATCH; r += 256) {
        float s = 0.f;
        const float* p = &g_partial[(size_t)r * CT];
        for (int c = 0; c < CT; c++) s += p[c];
        ce += 28.f + logf(s) - g_lab[r];
    }
    ce = blockReduceSum(ce, sm);
    float simv = (tid < 32) ? g_simpart[tid] : 0.f;
    simv = blockReduceSum(simv, sm);
    if (tid == 0) {
        out[0] = ce / (float)BATCH;
        out[1] = 2.f * simv / (float)BATCH;
    }
}

// ---------------- launch --------------------------------------------------------
extern "C" void kernel_launch(void* const* d_in, const int* in_sizes, int n_in,
                              void* d_out, int out_size) {
    const float* v = (const float*)d_in[0];
    const float* t = (const float*)d_in[1];
    const void*  labels = d_in[2];
    const float* W = (const float*)d_in[3];
    float* out = (float*)d_out;

    cudaFuncSetAttribute(gemm_main, cudaFuncAttributeMaxDynamicSharedMemorySize, SMEM_ALLOC);
    cudaFuncSetAttribute(sim_main,  cudaFuncAttributeMaxDynamicSharedMemorySize, SMEM_ALLOC);

    detect_labels_kernel<<<1, 32>>>(labels);
    prep_kernel<<<2 * BATCH, 256>>>(v, t);
    wnorm_kernel<<<(NCLS + 255) / 256, 256>>>(W);
    transpose_kernel<<<dim3(NCLSP / 32, FEAT / 32), dim3(32, 8)>>>(W);
    gemm_main<<<dim3(CT, 2 * BATCH / BM), 256, SMEM_ALLOC>>>();
    lab_kernel<<<2 * BATCH, 256>>>(labels);
    sim_main<<<dim3(BATCH / BN, BATCH / BM), 256, SMEM_ALLOC>>>(labels);
    finalize_kernel<<<1, 256>>>(out);
}

// round 12
// speedup vs baseline: 5.7861x; 2.1331x over previous
#include <cuda_runtime.h>
#include <cuda_bf16.h>
#include <math.h>
#include <stdint.h>

#define BATCH 1024
#define FEAT  2048
#define NCLS  11003
#define NCLSP 11008
#define CT    43            // ceil(11003/256)
#define BM 128
#define BN 256
#define BK 64               // bf16 elements per chunk
#define PITCH 144           // bytes per smem row (128 data + 16 pad)
#define A_BYTES (BM*PITCH)              // 18432
#define B_BYTES (BN*PITCH)              // 36864
#define STAGE_BYTES (A_BYTES + B_BYTES) // 55296
#define SMEM_ALLOC (2*STAGE_BYTES)      // 110592

// ---------------- scratch -----------------------------------------------------
__device__ __nv_bfloat16 g_emb[2 * BATCH * FEAT];       // normalized v,t rows (bf16)
__device__ __nv_bfloat16 g_Wt[(size_t)NCLSP * FEAT];    // raw W^T (bf16, padded 0)
__device__ float g_invwn[NCLSP];
__device__ float g_partial[2 * BATCH * CT];
__device__ float g_lab[2 * BATCH];
__device__ float g_simpart[32];
__device__ int   g_lab32;

// ---------------- helpers ------------------------------------------------------
static __device__ __forceinline__ uint32_t smem_u32(const void* p) {
    uint32_t a;
    asm("{ .reg .u64 t; cvta.to.shared.u64 t, %1; cvt.u32.u64 %0, t; }"
        : "=r"(a) : "l"(p));
    return a;
}
static __device__ __forceinline__ void cp16(uint32_t dst, const void* src) {
    asm volatile("cp.async.cg.shared.global [%0], [%1], 16;"
                 :: "r"(dst), "l"(src) : "memory");
}
__device__ __forceinline__ float blockReduceSum(float v, float* sm) {
    int tid = threadIdx.x;
    sm[tid] = v;
    __syncthreads();
    for (int s = blockDim.x >> 1; s > 0; s >>= 1) {
        if (tid < s) sm[tid] += sm[tid + s];
        __syncthreads();
    }
    float r = sm[0];
    __syncthreads();
    return r;
}
__device__ __forceinline__ int get_label(const void* labels, int i) {
    if (g_lab32) return ((const int*)labels)[i];
    return (int)(((const long long*)labels)[i]);
}
__device__ __forceinline__ float softplusf(float x) {
    return fmaxf(x, 0.f) + log1pf(__expf(-fabsf(x)));
}

#define LDSM4(r0, r1, r2, r3, addr) \
    asm volatile("ldmatrix.sync.aligned.m8n8.x4.shared.b16 {%0,%1,%2,%3}, [%4];" \
                 : "=r"(r0), "=r"(r1), "=r"(r2), "=r"(r3) : "r"(addr))

#define MMA_BF16(d, a0, a1, a2, a3, b0, b1) \
    asm volatile("mma.sync.aligned.m16n8k16.row.col.f32.bf16.bf16.f32 " \
                 "{%0,%1,%2,%3}, {%4,%5,%6,%7}, {%8,%9}, {%0,%1,%2,%3};" \
                 : "+f"(d[0]), "+f"(d[1]), "+f"(d[2]), "+f"(d[3]) \
                 : "r"(a0), "r"(a1), "r"(a2), "r"(a3), "r"(b0), "r"(b1))

// C[128x256] += A[128x2048] @ B[256x2048]^T, bf16 operands, fp32 accum.
// 8 warps (2m x 4n), warp tile 64x64, cp.async double-buffered BK=64, ldmatrix.
static __device__ __forceinline__ void gemm_mainloop_bf16(
        const __nv_bfloat16* __restrict__ Ag,
        const __nv_bfloat16* __restrict__ Bg,
        float (&acc)[4][8][4], float* smf) {
    const int tid = threadIdx.x;
    const int wid = tid >> 5, lane = tid & 31;
    const int wm = (wid >> 2) * 64, wn = (wid & 3) * 64;
    uint32_t sb = smem_u32(smf);

    // copy maps: 16B granules. A: 128 rows x 8 chunks = 1024; B: 256 x 8 = 2048.
    int aSm[4], aG[4], bSm[8], bG[8];
    #pragma unroll
    for (int i = 0; i < 4; i++) {
        int f = tid + i * 256, r = f >> 3, c = f & 7;
        aSm[i] = r * PITCH + c * 16;
        aG[i]  = r * FEAT + c * 8;
    }
    #pragma unroll
    for (int i = 0; i < 8; i++) {
        int f = tid + i * 256, r = f >> 3, c = f & 7;
        bSm[i] = r * PITCH + c * 16;
        bG[i]  = r * FEAT + c * 8;
    }
    uint32_t stBase[2] = { sb, sb + STAGE_BYTES };

    // ldmatrix per-lane bases
    uint32_t aLd = (uint32_t)((wm + (lane & 15)) * PITCH + ((lane >> 4) & 1) * 16);
    uint32_t bLd = (uint32_t)(A_BYTES +
                   (wn + (lane & 7) + ((lane >> 4) & 1) * 8) * PITCH +
                   ((lane >> 3) & 1) * 16);

    // prefetch stage 0
    #pragma unroll
    for (int i = 0; i < 4; i++) cp16(stBase[0] + aSm[i], Ag + aG[i]);
    #pragma unroll
    for (int i = 0; i < 8; i++) cp16(stBase[0] + A_BYTES + bSm[i], Bg + bG[i]);
    asm volatile("cp.async.commit_group;" ::: "memory");

    for (int s = 0; s < FEAT / BK; s++) {
        if (s + 1 < FEAT / BK) {
            int k0 = (s + 1) * BK, st = (s + 1) & 1;
            #pragma unroll
            for (int i = 0; i < 4; i++) cp16(stBase[st] + aSm[i], Ag + aG[i] + k0);
            #pragma unroll
            for (int i = 0; i < 8; i++) cp16(stBase[st] + A_BYTES + bSm[i], Bg + bG[i] + k0);
        }
        asm volatile("cp.async.commit_group;" ::: "memory");
        asm volatile("cp.async.wait_group 1;" ::: "memory");
        __syncthreads();

        uint32_t base = stBase[s & 1];
        #pragma unroll
        for (int kk = 0; kk < 4; kk++) {
            uint32_t a[4][4];
            #pragma unroll
            for (int mf = 0; mf < 4; mf++) {
                uint32_t ad = base + aLd + mf * (16 * PITCH) + kk * 32;
                LDSM4(a[mf][0], a[mf][1], a[mf][2], a[mf][3], ad);
            }
            #pragma unroll
            for (int p = 0; p < 4; p++) {
                uint32_t b0, b1, b2, b3;
                uint32_t bd = base + bLd + p * (16 * PITCH) + kk * 32;
                LDSM4(b0, b1, b2, b3, bd);
                #pragma unroll
                for (int mf = 0; mf < 4; mf++) {
                    MMA_BF16(acc[mf][2 * p],     a[mf][0], a[mf][1], a[mf][2], a[mf][3], b0, b1);
                    MMA_BF16(acc[mf][2 * p + 1], a[mf][0], a[mf][1], a[mf][2], a[mf][3], b2, b3);
                }
            }
        }
        __syncthreads();
    }
    asm volatile("cp.async.wait_group 0;" ::: "memory");
    __syncthreads();
}

// ---------------- label dtype detection ---------------------------------------
__global__ void detect_labels_kernel(const void* labels) {
    if (threadIdx.x == 0 && blockIdx.x == 0) {
        const long long* p = (const long long*)labels;
        int is32 = 0;
        for (int i = 0; i < 16; i++) {
            long long v = p[i];
            if (v < 0 || v >= (long long)NCLS) { is32 = 1; break; }
        }
        g_lab32 = is32;
    }
}

// ---------------- row L2 normalize -> bf16 g_emb -------------------------------
__global__ void prep_kernel(const float* __restrict__ v, const float* __restrict__ t) {
    __shared__ float sm[256];
    int b = blockIdx.x;
    const float* src = (b >= BATCH) ? t + (size_t)(b - BATCH) * FEAT
                                    : v + (size_t)b * FEAT;
    __nv_bfloat16* dst = g_emb + (size_t)b * FEAT;
    float s = 0.f;
    for (int k = threadIdx.x; k < FEAT; k += 256) { float x = src[k]; s += x * x; }
    s = blockReduceSum(s, sm);
    float inv = rsqrtf(s);
    for (int k = threadIdx.x; k < FEAT; k += 256)
        dst[k] = __float2bfloat16_rn(src[k] * inv);
}

// ---------------- transpose W -> bf16 g_Wt (raw, zero-padded) -------------------
__global__ void transpose_kernel(const float* __restrict__ W) {
    __shared__ float tile[32][33];
    int n = blockIdx.x * 32 + threadIdx.x;
    int k0 = blockIdx.y * 32;
    #pragma unroll
    for (int kk = 0; kk < 4; kk++) {
        int k = k0 + threadIdx.y + kk * 8;
        float val = 0.f;
        if (n < NCLS) val = W[(size_t)k * NCLS + n];
        tile[threadIdx.y + kk * 8][threadIdx.x] = val;
    }
    __syncthreads();
    #pragma unroll
    for (int kk = 0; kk < 4; kk++) {
        int nl = threadIdx.y + kk * 8;
        g_Wt[(size_t)(blockIdx.x * 32 + nl) * FEAT + k0 + threadIdx.x] =
            __float2bfloat16_rn(tile[threadIdx.x][nl]);
    }
}

// ---------------- inverse norms from contiguous bf16 rows of g_Wt --------------
__global__ void wnorm_kernel() {
    int wid = threadIdx.x >> 5, lane = threadIdx.x & 31;
    int j = blockIdx.x * 8 + wid;
    const uint4* p = (const uint4*)(g_Wt + (size_t)j * FEAT);   // 8 bf16 per uint4
    float s = 0.f;
    #pragma unroll
    for (int it = 0; it < 8; it++) {
        uint4 u = p[lane + it * 32];
        const __nv_bfloat162* h = (const __nv_bfloat162*)&u;
        #pragma unroll
        for (int q = 0; q < 4; q++) {
            float2 f = __bfloat1622float2(h[q]);
            s = fmaf(f.x, f.x, s);
            s = fmaf(f.y, f.y, s);
        }
    }
    #pragma unroll
    for (int o = 16; o > 0; o >>= 1) s += __shfl_xor_sync(0xffffffffu, s, o);
    if (lane == 0) g_invwn[j] = (s > 0.f) ? rsqrtf(s) : 0.f;
}

// ---------------- main GEMM (bf16 mma) + fused sumexp epilogue ------------------
__global__ __launch_bounds__(256, 1) void gemm_main() {
    extern __shared__ float smf[];
    int colBase = blockIdx.x * BN;
    int rowBase = blockIdx.y * BM;
    const __nv_bfloat16* Ag = g_emb + (size_t)rowBase * FEAT;
    const __nv_bfloat16* Bg = g_Wt + (size_t)colBase * FEAT;

    float acc[4][8][4];
    #pragma unroll
    for (int m = 0; m < 4; m++)
        #pragma unroll
        for (int n = 0; n < 8; n++)
            #pragma unroll
            for (int q = 0; q < 4; q++) acc[m][n][q] = 0.f;

    gemm_mainloop_bf16(Ag, Bg, acc, smf);

    int tid = threadIdx.x;
    int wid = tid >> 5, lane = tid & 31;
    int wm = (wid >> 2) * 64, wn = (wid & 3) * 64;
    int lq = lane >> 2, lk = lane & 3;

    float rs[4][2];
    #pragma unroll
    for (int mf = 0; mf < 4; mf++) { rs[mf][0] = 0.f; rs[mf][1] = 0.f; }
    #pragma unroll
    for (int nf = 0; nf < 8; nf++) {
        int c = colBase + wn + nf * 8 + 2 * lk;
        float w0 = 28.f * g_invwn[c];
        float w1 = 28.f * g_invwn[c + 1];
        bool in0 = (c < NCLS), in1 = (c + 1 < NCLS);
        #pragma unroll
        for (int mf = 0; mf < 4; mf++) {
            float e0 = in0 ? __expf(fmaf(w0, acc[mf][nf][0], -28.f)) : 0.f;
            float e1 = in1 ? __expf(fmaf(w1, acc[mf][nf][1], -28.f)) : 0.f;
            float e2 = in0 ? __expf(fmaf(w0, acc[mf][nf][2], -28.f)) : 0.f;
            float e3 = in1 ? __expf(fmaf(w1, acc[mf][nf][3], -28.f)) : 0.f;
            rs[mf][0] += e0 + e1;
            rs[mf][1] += e2 + e3;
        }
    }
    #pragma unroll
    for (int mf = 0; mf < 4; mf++)
        #pragma unroll
        for (int h = 0; h < 2; h++) {
            rs[mf][h] += __shfl_xor_sync(0xffffffffu, rs[mf][h], 1);
            rs[mf][h] += __shfl_xor_sync(0xffffffffu, rs[mf][h], 2);
        }
    float* red = smf;  // 512 floats
    if (lk == 0) {
        #pragma unroll
        for (int mf = 0; mf < 4; mf++)
            #pragma unroll
            for (int h = 0; h < 2; h++)
                red[(wm + mf * 16 + lq + 8 * h) * 4 + (wid & 3)] = rs[mf][h];
    }
    __syncthreads();
    if (tid < 128) {
        float s = red[tid * 4] + red[tid * 4 + 1] + red[tid * 4 + 2] + red[tid * 4 + 3];
        g_partial[(size_t)(rowBase + tid) * CT + blockIdx.x] = s;
    }
}

// ---------------- sim GEMM (bf16 mma) + fused masked softplus -------------------
__global__ __launch_bounds__(256, 1) void sim_main(const void* labels) {
    extern __shared__ float smf[];
    int colBase = blockIdx.x * BN;   // textual
    int rowBase = blockIdx.y * BM;   // visual
    const __nv_bfloat16* Ag = g_emb + (size_t)rowBase * FEAT;
    const __nv_bfloat16* Bg = g_emb + (size_t)(BATCH + colBase) * FEAT;

    float acc[4][8][4];
    #pragma unroll
    for (int m = 0; m < 4; m++)
        #pragma unroll
        for (int n = 0; n < 8; n++)
            #pragma unroll
            for (int q = 0; q < 4; q++) acc[m][n][q] = 0.f;

    gemm_mainloop_bf16(Ag, Bg, acc, smf);

    int tid = threadIdx.x;
    int wid = tid >> 5, lane = tid & 31;
    int wm = (wid >> 2) * 64, wn = (wid & 3) * 64;
    int lq = lane >> 2, lk = lane & 3;

    int* scol = (int*)(smf + 1024);
    int* srow = (int*)(smf + 1024 + 256);
    scol[tid] = get_label(labels, colBase + tid);
    if (tid < 128) srow[tid] = get_label(labels, rowBase + tid);
    __syncthreads();

    float s = 0.f;
    #pragma unroll
    for (int mf = 0; mf < 4; mf++) {
        int r0 = wm + mf * 16 + lq;
        int la = srow[r0], lb = srow[r0 + 8];
        #pragma unroll
        for (int nf = 0; nf < 8; nf++) {
            int c = wn + nf * 8 + 2 * lk;
            int lc0 = scol[c], lc1 = scol[c + 1];
            float x0 = acc[mf][nf][0], x1 = acc[mf][nf][1];
            float x2 = acc[mf][nf][2], x3 = acc[mf][nf][3];
            s += softplusf((la == lc0) ? (-10.f * (x0 - 0.6f)) : (40.f * (x0 - 0.4f)));
            s += softplusf((la == lc1) ? (-10.f * (x1 - 0.6f)) : (40.f * (x1 - 0.4f)));
            s += softplusf((lb == lc0) ? (-10.f * (x2 - 0.6f)) : (40.f * (x2 - 0.4f)));
            s += softplusf((lb == lc1) ? (-10.f * (x3 - 0.6f)) : (40.f * (x3 - 0.4f)));
        }
    }
    __syncthreads();
    s = blockReduceSum(s, smf);
    if (tid == 0) g_simpart[blockIdx.y * 4 + blockIdx.x] = s;
}

// ---------------- label logits --------------------------------------------------
__global__ void lab_kernel(const void* labels) {
    __shared__ float sm[256];
    int b = blockIdx.x;  // 0..2047
    const __nv_bfloat16* e = g_emb + (size_t)b * FEAT;
    int lab = get_label(labels, b & (BATCH - 1));
    const __nv_bfloat16* w = g_Wt + (size_t)lab * FEAT;
    float s = 0.f;
    for (int k = threadIdx.x; k < FEAT; k += 256)
        s = fmaf(__bfloat162float(e[k]), __bfloat162float(w[k]), s);
    s = blockReduceSum(s, sm);
    if (threadIdx.x == 0) g_lab[b] = 28.f * s * g_invwn[lab];
}

// ---------------- finalize ------------------------------------------------------
__global__ void finalize_kernel(float* __restrict__ out) {
    __shared__ float sm[256];
    int tid = threadIdx.x;
    float ce = 0.f;
    for (int r = tid; r < 2 * BATCH; r += 256) {
        float s = 0.f;
        const float* p = &g_partial[(size_t)r * CT];
        for (int c = 0; c < CT; c++) s += p[c];
        ce += 28.f + logf(s) - g_lab[r];
    }
    ce = blockReduceSum(ce, sm);
    float simv = (tid < 32) ? g_simpart[tid] : 0.f;
    simv = blockReduceSum(simv, sm);
    if (tid == 0) {
        out[0] = ce / (float)BATCH;
        out[1] = 2.f * simv / (float)BATCH;
    }
}

// ---------------- launch --------------------------------------------------------
extern "C" void kernel_launch(void* const* d_in, const int* in_sizes, int n_in,
                              void* d_out, int out_size) {
    const float* v = (const float*)d_in[0];
    const float* t = (const float*)d_in[1];
    const void*  labels = d_in[2];
    const float* W = (const float*)d_in[3];
    float* out = (float*)d_out;

    cudaFuncSetAttribute(gemm_main, cudaFuncAttributeMaxDynamicSharedMemorySize, SMEM_ALLOC);
    cudaFuncSetAttribute(sim_main,  cudaFuncAttributeMaxDynamicSharedMemorySize, SMEM_ALLOC);

    detect_labels_kernel<<<1, 32>>>(labels);
    prep_kernel<<<2 * BATCH, 256>>>(v, t);
    transpose_kernel<<<dim3(NCLSP / 32, FEAT / 32), dim3(32, 8)>>>(W);
    wnorm_kernel<<<NCLSP / 8, 256>>>();
    gemm_main<<<dim3(CT, 2 * BATCH / BM), 256, SMEM_ALLOC>>>();
    lab_kernel<<<2 * BATCH, 256>>>(labels);
    sim_main<<<dim3(BATCH / BN, BATCH / BM), 256, SMEM_ALLOC>>>(labels);
    finalize_kernel<<<1, 256>>>(out);
}

// round 13
// speedup vs baseline: 6.8230x; 1.1792x over previous
#include <cuda_runtime.h>
#include <cuda_bf16.h>
#include <math.h>
#include <stdint.h>

#define BATCH 1024
#define FEAT  2048
#define NCLS  11003
#define NCLSP 11008
#define CT    43            // ceil(11003/256)
#define BM 128
#define BN 256
#define BK 64               // bf16 elements per chunk
#define NITER (FEAT/BK)     // 32
#define PITCH 144           // bytes per smem row (128 data + 16 pad)
#define A_BYTES (BM*PITCH)              // 18432
#define B_BYTES (BN*PITCH)              // 36864
#define STAGE_BYTES (A_BYTES + B_BYTES) // 55296
#define SMEM_ALLOC (3*STAGE_BYTES)      // 165888

#define NB_GEMM 688          // CT * 16
#define NB_SIM  32           // (1024/256) * (1024/128)
#define NB_LAB  256          // 2048 rows / 8 per block

// ---------------- scratch -----------------------------------------------------
__device__ __nv_bfloat16 g_emb[2 * BATCH * FEAT];       // normalized v,t rows (bf16)
__device__ __nv_bfloat16 g_Wt[(size_t)NCLSP * FEAT];    // raw W^T (bf16, padded 0)
__device__ float g_invwn[NCLSP];
__device__ float g_partial[2 * BATCH * CT];
__device__ float g_lab[2 * BATCH];
__device__ float g_simpart[NB_SIM];
__device__ int   g_lab32;

// ---------------- helpers ------------------------------------------------------
static __device__ __forceinline__ uint32_t smem_u32(const void* p) {
    uint32_t a;
    asm("{ .reg .u64 t; cvta.to.shared.u64 t, %1; cvt.u32.u64 %0, t; }"
        : "=r"(a) : "l"(p));
    return a;
}
static __device__ __forceinline__ void cp16(uint32_t dst, const void* src) {
    asm volatile("cp.async.cg.shared.global [%0], [%1], 16;"
                 :: "r"(dst), "l"(src) : "memory");
}
__device__ __forceinline__ float blockReduceSum(float v, float* sm) {
    int tid = threadIdx.x;
    sm[tid] = v;
    __syncthreads();
    for (int s = blockDim.x >> 1; s > 0; s >>= 1) {
        if (tid < s) sm[tid] += sm[tid + s];
        __syncthreads();
    }
    float r = sm[0];
    __syncthreads();
    return r;
}
__device__ __forceinline__ int get_label(const void* labels, int i) {
    if (g_lab32) return ((const int*)labels)[i];
    return (int)(((const long long*)labels)[i]);
}
__device__ __forceinline__ float softplusf(float x) {
    return fmaxf(x, 0.f) + log1pf(__expf(-fabsf(x)));
}

#define LDSM4(r0, r1, r2, r3, addr) \
    asm volatile("ldmatrix.sync.aligned.m8n8.x4.shared.b16 {%0,%1,%2,%3}, [%4];" \
                 : "=r"(r0), "=r"(r1), "=r"(r2), "=r"(r3) : "r"(addr))

#define MMA_BF16(d, a0, a1, a2, a3, b0, b1) \
    asm volatile("mma.sync.aligned.m16n8k16.row.col.f32.bf16.bf16.f32 " \
                 "{%0,%1,%2,%3}, {%4,%5,%6,%7}, {%8,%9}, {%0,%1,%2,%3};" \
                 : "+f"(d[0]), "+f"(d[1]), "+f"(d[2]), "+f"(d[3]) \
                 : "r"(a0), "r"(a1), "r"(a2), "r"(a3), "r"(b0), "r"(b1))

// C[128x256] += A[128x2048] @ B[256x2048]^T, bf16 operands, fp32 accum.
// 8 warps (2m x 4n), warp tile 64x64. 3-stage cp.async pipeline, ONE sync/chunk.
static __device__ __forceinline__ void gemm_mainloop_bf16(
        const __nv_bfloat16* __restrict__ Ag,
        const __nv_bfloat16* __restrict__ Bg,
        float (&acc)[4][8][4], float* smf) {
    const int tid = threadIdx.x;
    const int wid = tid >> 5, lane = tid & 31;
    const int wm = (wid >> 2) * 64, wn = (wid & 3) * 64;
    uint32_t sb = smem_u32(smf);

    int aSm[4], aG[4], bSm[8], bG[8];
    #pragma unroll
    for (int i = 0; i < 4; i++) {
        int f = tid + i * 256, r = f >> 3, c = f & 7;
        aSm[i] = r * PITCH + c * 16;
        aG[i]  = r * FEAT + c * 8;
    }
    #pragma unroll
    for (int i = 0; i < 8; i++) {
        int f = tid + i * 256, r = f >> 3, c = f & 7;
        bSm[i] = r * PITCH + c * 16;
        bG[i]  = r * FEAT + c * 8;
    }
    uint32_t stBase[3] = { sb, sb + STAGE_BYTES, sb + 2u * STAGE_BYTES };

    uint32_t aLd = (uint32_t)((wm + (lane & 15)) * PITCH + ((lane >> 4) & 1) * 16);
    uint32_t bLd = (uint32_t)(A_BYTES +
                   (wn + (lane & 7) + ((lane >> 4) & 1) * 8) * PITCH +
                   ((lane >> 3) & 1) * 16);

    // prologue: stages 0 and 1
    #pragma unroll
    for (int st = 0; st < 2; st++) {
        int k0 = st * BK;
        #pragma unroll
        for (int i = 0; i < 4; i++) cp16(stBase[st] + aSm[i], Ag + aG[i] + k0);
        #pragma unroll
        for (int i = 0; i < 8; i++) cp16(stBase[st] + A_BYTES + bSm[i], Bg + bG[i] + k0);
        asm volatile("cp.async.commit_group;" ::: "memory");
    }

    for (int s = 0; s < NITER; s++) {
        asm volatile("cp.async.wait_group 1;" ::: "memory");  // stage s arrived
        __syncthreads();                                       // all warps past compute(s-1)
        if (s + 2 < NITER) {                                   // refill stage (s-1)%3
            int k0 = (s + 2) * BK;
            uint32_t base = stBase[(s + 2) % 3];
            #pragma unroll
            for (int i = 0; i < 4; i++) cp16(base + aSm[i], Ag + aG[i] + k0);
            #pragma unroll
            for (int i = 0; i < 8; i++) cp16(base + A_BYTES + bSm[i], Bg + bG[i] + k0);
        }
        asm volatile("cp.async.commit_group;" ::: "memory");   // (empty when done)

        uint32_t base = stBase[s % 3];
        #pragma unroll
        for (int kk = 0; kk < 4; kk++) {
            uint32_t a[4][4];
            #pragma unroll
            for (int mf = 0; mf < 4; mf++) {
                uint32_t ad = base + aLd + mf * (16 * PITCH) + kk * 32;
                LDSM4(a[mf][0], a[mf][1], a[mf][2], a[mf][3], ad);
            }
            #pragma unroll
            for (int p = 0; p < 4; p++) {
                uint32_t b0, b1, b2, b3;
                uint32_t bd = base + bLd + p * (16 * PITCH) + kk * 32;
                LDSM4(b0, b1, b2, b3, bd);
                #pragma unroll
                for (int mf = 0; mf < 4; mf++) {
                    MMA_BF16(acc[mf][2 * p],     a[mf][0], a[mf][1], a[mf][2], a[mf][3], b0, b1);
                    MMA_BF16(acc[mf][2 * p + 1], a[mf][0], a[mf][1], a[mf][2], a[mf][3], b2, b3);
                }
            }
        }
    }
    __syncthreads();   // epilogue reuses stage-0 smem; last compute used stage 31%3==1
}

// ---------------- label dtype detection ---------------------------------------
__global__ void detect_labels_kernel(const void* labels) {
    if (threadIdx.x == 0 && blockIdx.x == 0) {
        const long long* p = (const long long*)labels;
        int is32 = 0;
        for (int i = 0; i < 16; i++) {
            long long v = p[i];
            if (v < 0 || v >= (long long)NCLS) { is32 = 1; break; }
        }
        g_lab32 = is32;
    }
}

// ---------------- row L2 normalize -> bf16 g_emb (vectorized) -------------------
__global__ void prep_kernel(const float* __restrict__ v, const float* __restrict__ t) {
    __shared__ float sm[256];
    int b = blockIdx.x;
    const float4* src = (const float4*)((b >= BATCH) ? t + (size_t)(b - BATCH) * FEAT
                                                     : v + (size_t)b * FEAT);
    uint2* dst = (uint2*)(g_emb + (size_t)b * FEAT);   // 4 bf16 per uint2
    int tid = threadIdx.x;
    float4 x0 = src[tid], x1 = src[tid + 256];
    float s = x0.x * x0.x + x0.y * x0.y + x0.z * x0.z + x0.w * x0.w
            + x1.x * x1.x + x1.y * x1.y + x1.z * x1.z + x1.w * x1.w;
    s = blockReduceSum(s, sm);
    float inv = rsqrtf(s);
    __nv_bfloat162 h0 = __floats2bfloat162_rn(x0.x * inv, x0.y * inv);
    __nv_bfloat162 h1 = __floats2bfloat162_rn(x0.z * inv, x0.w * inv);
    __nv_bfloat162 h2 = __floats2bfloat162_rn(x1.x * inv, x1.y * inv);
    __nv_bfloat162 h3 = __floats2bfloat162_rn(x1.z * inv, x1.w * inv);
    uint2 o0, o1;
    o0.x = *(uint32_t*)&h0; o0.y = *(uint32_t*)&h1;
    o1.x = *(uint32_t*)&h2; o1.y = *(uint32_t*)&h3;
    dst[tid] = o0;
    dst[tid + 256] = o1;
}

// ---------------- transpose W -> bf16 g_Wt + exact norms (no atomics) -----------
// One block per 32-column strip; iterates all K. grid = 344, block (32,8).
__global__ void transpose_norm_kernel(const float* __restrict__ W) {
    __shared__ float tile[64][33];
    int tx = threadIdx.x, ty = threadIdx.y;
    int n = blockIdx.x * 32 + tx;
    bool nok = (n < NCLS);
    float acc4[4] = {0.f, 0.f, 0.f, 0.f};

    for (int kb = 0; kb < FEAT / 64; kb++) {
        int k0 = kb * 64;
        #pragma unroll
        for (int i = 0; i < 8; i++) {
            int k = k0 + ty + i * 8;
            tile[ty + i * 8][tx] = nok ? W[(size_t)k * NCLS + n] : 0.f;
        }
        __syncthreads();
        #pragma unroll
        for (int kk = 0; kk < 4; kk++) {
            int nl = ty + kk * 8;
            int gn = blockIdx.x * 32 + nl;
            float f0 = tile[tx * 2][nl], f1 = tile[tx * 2 + 1][nl];
            __nv_bfloat162 h = __floats2bfloat162_rn(f0, f1);
            *(__nv_bfloat162*)(g_Wt + (size_t)gn * FEAT + k0 + tx * 2) = h;
            float2 ff = __bfloat1622float2(h);
            acc4[kk] = fmaf(ff.x, ff.x, fmaf(ff.y, ff.y, acc4[kk]));
        }
        __syncthreads();
    }
    #pragma unroll
    for (int kk = 0; kk < 4; kk++) {
        float s = acc4[kk];
        #pragma unroll
        for (int o = 16; o > 0; o >>= 1) s += __shfl_xor_sync(0xffffffffu, s, o);
        if (tx == 0)
            g_invwn[blockIdx.x * 32 + ty + kk * 8] = rsqrtf(fmaxf(s, 1e-20f));
    }
}

// ---------------- mega kernel: gemm (688) + sim (32) + lab (256) ----------------
__global__ __launch_bounds__(256, 1) void mega_kernel(const void* labels) {
    extern __shared__ float smf[];
    int bid = blockIdx.x;
    int tid = threadIdx.x;

    if (bid < NB_GEMM) {
        // ---- classifier GEMM tile + fused sumexp epilogue ----
        int colBase = (bid % CT) * BN;
        int rowBase = (bid / CT) * BM;
        const __nv_bfloat16* Ag = g_emb + (size_t)rowBase * FEAT;
        const __nv_bfloat16* Bg = g_Wt + (size_t)colBase * FEAT;

        float acc[4][8][4];
        #pragma unroll
        for (int m = 0; m < 4; m++)
            #pragma unroll
            for (int n = 0; n < 8; n++)
                #pragma unroll
                for (int q = 0; q < 4; q++) acc[m][n][q] = 0.f;

        gemm_mainloop_bf16(Ag, Bg, acc, smf);

        int wid = tid >> 5, lane = tid & 31;
        int wm = (wid >> 2) * 64, wn = (wid & 3) * 64;
        int lq = lane >> 2, lk = lane & 3;

        float rs[4][2];
        #pragma unroll
        for (int mf = 0; mf < 4; mf++) { rs[mf][0] = 0.f; rs[mf][1] = 0.f; }
        #pragma unroll
        for (int nf = 0; nf < 8; nf++) {
            int c = colBase + wn + nf * 8 + 2 * lk;
            float w0 = 28.f * g_invwn[c];
            float w1 = 28.f * g_invwn[c + 1];
            bool in0 = (c < NCLS), in1 = (c + 1 < NCLS);
            #pragma unroll
            for (int mf = 0; mf < 4; mf++) {
                float e0 = in0 ? __expf(fmaf(w0, acc[mf][nf][0], -28.f)) : 0.f;
                float e1 = in1 ? __expf(fmaf(w1, acc[mf][nf][1], -28.f)) : 0.f;
                float e2 = in0 ? __expf(fmaf(w0, acc[mf][nf][2], -28.f)) : 0.f;
                float e3 = in1 ? __expf(fmaf(w1, acc[mf][nf][3], -28.f)) : 0.f;
                rs[mf][0] += e0 + e1;
                rs[mf][1] += e2 + e3;
            }
        }
        #pragma unroll
        for (int mf = 0; mf < 4; mf++)
            #pragma unroll
            for (int h = 0; h < 2; h++) {
                rs[mf][h] += __shfl_xor_sync(0xffffffffu, rs[mf][h], 1);
                rs[mf][h] += __shfl_xor_sync(0xffffffffu, rs[mf][h], 2);
            }
        float* red = smf;  // 512 floats (stage-0 region; safe after final sync)
        if (lk == 0) {
            #pragma unroll
            for (int mf = 0; mf < 4; mf++)
                #pragma unroll
                for (int h = 0; h < 2; h++)
                    red[(wm + mf * 16 + lq + 8 * h) * 4 + (wid & 3)] = rs[mf][h];
        }
        __syncthreads();
        if (tid < 128) {
            float s = red[tid * 4] + red[tid * 4 + 1] + red[tid * 4 + 2] + red[tid * 4 + 3];
            g_partial[(size_t)(rowBase + tid) * CT + (bid % CT)] = s;
        }
    } else if (bid < NB_GEMM + NB_SIM) {
        // ---- similarity GEMM tile + fused masked softplus ----
        int i = bid - NB_GEMM;
        int colBase = (i % 4) * BN;   // textual
        int rowBase = (i / 4) * BM;   // visual
        const __nv_bfloat16* Ag = g_emb + (size_t)rowBase * FEAT;
        const __nv_bfloat16* Bg = g_emb + (size_t)(BATCH + colBase) * FEAT;

        float acc[4][8][4];
        #pragma unroll
        for (int m = 0; m < 4; m++)
            #pragma unroll
            for (int n = 0; n < 8; n++)
                #pragma unroll
                for (int q = 0; q < 4; q++) acc[m][n][q] = 0.f;

        gemm_mainloop_bf16(Ag, Bg, acc, smf);

        int wid = tid >> 5, lane = tid & 31;
        int wm = (wid >> 2) * 64, wn = (wid & 3) * 64;
        int lq = lane >> 2, lk = lane & 3;

        int* scol = (int*)(smf + 1024);
        int* srow = (int*)(smf + 1024 + 256);
        scol[tid] = get_label(labels, colBase + tid);
        if (tid < 128) srow[tid] = get_label(labels, rowBase + tid);
        __syncthreads();

        float s = 0.f;
        #pragma unroll
        for (int mf = 0; mf < 4; mf++) {
            int r0 = wm + mf * 16 + lq;
            int la = srow[r0], lb = srow[r0 + 8];
            #pragma unroll
            for (int nf = 0; nf < 8; nf++) {
                int c = wn + nf * 8 + 2 * lk;
                int lc0 = scol[c], lc1 = scol[c + 1];
                float x0 = acc[mf][nf][0], x1 = acc[mf][nf][1];
                float x2 = acc[mf][nf][2], x3 = acc[mf][nf][3];
                s += softplusf((la == lc0) ? (-10.f * (x0 - 0.6f)) : (40.f * (x0 - 0.4f)));
                s += softplusf((la == lc1) ? (-10.f * (x1 - 0.6f)) : (40.f * (x1 - 0.4f)));
                s += softplusf((lb == lc0) ? (-10.f * (x2 - 0.6f)) : (40.f * (x2 - 0.4f)));
                s += softplusf((lb == lc1) ? (-10.f * (x3 - 0.6f)) : (40.f * (x3 - 0.4f)));
            }
        }
        __syncthreads();
        s = blockReduceSum(s, smf);
        if (tid == 0) g_simpart[i] = s;
    } else {
        // ---- label logits: 8 rows per block, 1 warp per row ----
        int idx = bid - (NB_GEMM + NB_SIM);      // 0..255
        int w = tid >> 5, lane = tid & 31;
        int row = idx * 8 + w;                   // 0..2047
        int lab = get_label(labels, row & (BATCH - 1));
        const uint4* e  = (const uint4*)(g_emb + (size_t)row * FEAT);
        const uint4* wv = (const uint4*)(g_Wt + (size_t)lab * FEAT);
        float s = 0.f;
        #pragma unroll
        for (int it = 0; it < 8; it++) {
            uint4 ue = e[lane + it * 32];
            uint4 uw = wv[lane + it * 32];
            const __nv_bfloat162* he = (const __nv_bfloat162*)&ue;
            const __nv_bfloat162* hw = (const __nv_bfloat162*)&uw;
            #pragma unroll
            for (int q = 0; q < 4; q++) {
                float2 fe = __bfloat1622float2(he[q]);
                float2 fw = __bfloat1622float2(hw[q]);
                s = fmaf(fe.x, fw.x, s);
                s = fmaf(fe.y, fw.y, s);
            }
        }
        #pragma unroll
        for (int o = 16; o > 0; o >>= 1) s += __shfl_xor_sync(0xffffffffu, s, o);
        if (lane == 0) g_lab[row] = 28.f * s * g_invwn[lab];
    }
}

// ---------------- finalize ------------------------------------------------------
__global__ void finalize_kernel(float* __restrict__ out) {
    __shared__ float sm[256];
    int tid = threadIdx.x;
    float ce = 0.f;
    for (int r = tid; r < 2 * BATCH; r += 256) {
        float s = 0.f;
        const float* p = &g_partial[(size_t)r * CT];
        for (int c = 0; c < CT; c++) s += p[c];
        ce += 28.f + logf(s) - g_lab[r];
    }
    ce = blockReduceSum(ce, sm);
    float simv = (tid < NB_SIM) ? g_simpart[tid] : 0.f;
    simv = blockReduceSum(simv, sm);
    if (tid == 0) {
        out[0] = ce / (float)BATCH;
        out[1] = 2.f * simv / (float)BATCH;
    }
}

// ---------------- launch --------------------------------------------------------
extern "C" void kernel_launch(void* const* d_in, const int* in_sizes, int n_in,
                              void* d_out, int out_size) {
    const float* v = (const float*)d_in[0];
    const float* t = (const float*)d_in[1];
    const void*  labels = d_in[2];
    const float* W = (const float*)d_in[3];
    float* out = (float*)d_out;

    cudaFuncSetAttribute(mega_kernel, cudaFuncAttributeMaxDynamicSharedMemorySize,
                         SMEM_ALLOC);

    detect_labels_kernel<<<1, 32>>>(labels);
    prep_kernel<<<2 * BATCH, 256>>>(v, t);
    transpose_norm_kernel<<<NCLSP / 32, dim3(32, 8)>>>(W);
    mega_kernel<<<NB_GEMM + NB_SIM + NB_LAB, 256, SMEM_ALLOC>>>(labels);
    finalize_kernel<<<1, 256>>>(out);
}

// round 15
// speedup vs baseline: 7.1876x; 1.0534x over previous
#include <cuda_runtime.h>
#include <cuda_bf16.h>
#include <math.h>
#include <stdint.h>

#define BATCH 1024
#define FEAT  2048
#define NCLS  11003
#define NCLSP 11008
#define CTN   86            // ceil(11003/128)
#define BM 128
#define BN 128
#define BK 64               // bf16 elements per chunk
#define NITER (FEAT/BK)     // 32
#define PITCH 144           // bytes per smem row (128 data + 16 pad)
#define A_BYTES (BM*PITCH)              // 18432
#define B_BYTES (BN*PITCH)              // 18432
#define STAGE_BYTES (A_BYTES + B_BYTES) // 36864
#define SMEM_ALLOC (3*STAGE_BYTES)      // 110592 -> 2 CTAs/SM

#define NB_GEMM 1376         // 16 row-tiles * 86 col-tiles
#define NB_SIM  64           // 8 x 8 tiles of 128
#define NB_LAB  256          // 2048 rows / 8 per block

// ---------------- scratch -----------------------------------------------------
__device__ __nv_bfloat16 g_emb[2 * BATCH * FEAT];       // normalized v,t rows (bf16)
__device__ __nv_bfloat16 g_Wt[(size_t)NCLSP * FEAT];    // raw W^T (bf16, padded 0)
__device__ float g_invwn[NCLSP];
__device__ float g_partial[2 * BATCH * CTN];
__device__ float g_lab[2 * BATCH];
__device__ float g_simpart[NB_SIM];
__device__ int   g_lab32;

// ---------------- helpers ------------------------------------------------------
static __device__ __forceinline__ uint32_t smem_u32(const void* p) {
    uint32_t a;
    asm("{ .reg .u64 t; cvta.to.shared.u64 t, %1; cvt.u32.u64 %0, t; }"
        : "=r"(a) : "l"(p));
    return a;
}
static __device__ __forceinline__ void cp16(uint32_t dst, const void* src) {
    asm volatile("cp.async.cg.shared.global [%0], [%1], 16;"
                 :: "r"(dst), "l"(src) : "memory");
}
__device__ __forceinline__ float blockReduceSum(float v, float* sm) {
    int tid = threadIdx.x;
    sm[tid] = v;
    __syncthreads();
    for (int s = blockDim.x >> 1; s > 0; s >>= 1) {
        if (tid < s) sm[tid] += sm[tid + s];
        __syncthreads();
    }
    float r = sm[0];
    __syncthreads();
    return r;
}
__device__ __forceinline__ int get_label(const void* labels, int i) {
    if (g_lab32) return ((const int*)labels)[i];
    return (int)(((const long long*)labels)[i]);
}
__device__ __forceinline__ float softplusf(float x) {
    return fmaxf(x, 0.f) + log1pf(__expf(-fabsf(x)));
}

#define LDSM4(r0, r1, r2, r3, addr) \
    asm volatile("ldmatrix.sync.aligned.m8n8.x4.shared.b16 {%0,%1,%2,%3}, [%4];" \
                 : "=r"(r0), "=r"(r1), "=r"(r2), "=r"(r3) : "r"(addr))

#define MMA_BF16(d, a0, a1, a2, a3, b0, b1) \
    asm volatile("mma.sync.aligned.m16n8k16.row.col.f32.bf16.bf16.f32 " \
                 "{%0,%1,%2,%3}, {%4,%5,%6,%7}, {%8,%9}, {%0,%1,%2,%3};" \
                 : "+f"(d[0]), "+f"(d[1]), "+f"(d[2]), "+f"(d[3]) \
                 : "r"(a0), "r"(a1), "r"(a2), "r"(a3), "r"(b0), "r"(b1))

// C[128x128] += A[128x2048] @ B[128x2048]^T, bf16 operands, fp32 accum.
// 8 warps (2m x 4n), warp tile 64x32. 3-stage cp.async pipeline, one sync/chunk.
static __device__ __forceinline__ void gemm_mainloop_bf16(
        const __nv_bfloat16* __restrict__ Ag,
        const __nv_bfloat16* __restrict__ Bg,
        float (&acc)[4][4][4], float* smf) {
    const int tid = threadIdx.x;
    const int wid = tid >> 5, lane = tid & 31;
    const int wm = (wid >> 2) * 64, wn = (wid & 3) * 32;
    uint32_t sb = smem_u32(smf);

    int aSm[4], aG[4], bSm[4], bG[4];
    #pragma unroll
    for (int i = 0; i < 4; i++) {
        int f = tid + i * 256, r = f >> 3, c = f & 7;
        aSm[i] = r * PITCH + c * 16;
        aG[i]  = r * FEAT + c * 8;
        bSm[i] = aSm[i];
        bG[i]  = aG[i];
    }
    uint32_t stBase[3] = { sb, sb + STAGE_BYTES, sb + 2u * STAGE_BYTES };

    uint32_t aLd = (uint32_t)((wm + (lane & 15)) * PITCH + ((lane >> 4) & 1) * 16);
    uint32_t bLd = (uint32_t)(A_BYTES +
                   (wn + (lane & 7) + ((lane >> 4) & 1) * 8) * PITCH +
                   ((lane >> 3) & 1) * 16);

    // prologue: stages 0 and 1
    #pragma unroll
    for (int st = 0; st < 2; st++) {
        int k0 = st * BK;
        #pragma unroll
        for (int i = 0; i < 4; i++) cp16(stBase[st] + aSm[i], Ag + aG[i] + k0);
        #pragma unroll
        for (int i = 0; i < 4; i++) cp16(stBase[st] + A_BYTES + bSm[i], Bg + bG[i] + k0);
        asm volatile("cp.async.commit_group;" ::: "memory");
    }

    for (int s = 0; s < NITER; s++) {
        asm volatile("cp.async.wait_group 1;" ::: "memory");
        __syncthreads();
        if (s + 2 < NITER) {
            int k0 = (s + 2) * BK;
            uint32_t base = stBase[(s + 2) % 3];
            #pragma unroll
            for (int i = 0; i < 4; i++) cp16(base + aSm[i], Ag + aG[i] + k0);
            #pragma unroll
            for (int i = 0; i < 4; i++) cp16(base + A_BYTES + bSm[i], Bg + bG[i] + k0);
        }
        asm volatile("cp.async.commit_group;" ::: "memory");

        uint32_t base = stBase[s % 3];
        #pragma unroll
        for (int kk = 0; kk < 4; kk++) {
            uint32_t b[8];
            LDSM4(b[0], b[1], b[2], b[3], base + bLd + kk * 32);
            LDSM4(b[4], b[5], b[6], b[7], base + bLd + 16 * PITCH + kk * 32);
            #pragma unroll
            for (int mf = 0; mf < 4; mf++) {
                uint32_t a0, a1, a2, a3;
                LDSM4(a0, a1, a2, a3, base + aLd + mf * (16 * PITCH) + kk * 32);
                MMA_BF16(acc[mf][0], a0, a1, a2, a3, b[0], b[1]);
                MMA_BF16(acc[mf][1], a0, a1, a2, a3, b[2], b[3]);
                MMA_BF16(acc[mf][2], a0, a1, a2, a3, b[4], b[5]);
                MMA_BF16(acc[mf][3], a0, a1, a2, a3, b[6], b[7]);
            }
        }
    }
    __syncthreads();   // smem reusable by epilogue after this
}

// ---------------- label dtype detection ---------------------------------------
__global__ void detect_labels_kernel(const void* labels) {
    if (threadIdx.x == 0 && blockIdx.x == 0) {
        const long long* p = (const long long*)labels;
        int is32 = 0;
        for (int i = 0; i < 16; i++) {
            long long v = p[i];
            if (v < 0 || v >= (long long)NCLS) { is32 = 1; break; }
        }
        g_lab32 = is32;
    }
}

// ---------------- row L2 normalize -> bf16 g_emb (vectorized) -------------------
__global__ void prep_kernel(const float* __restrict__ v, const float* __restrict__ t) {
    __shared__ float sm[256];
    int b = blockIdx.x;
    const float4* src = (const float4*)((b >= BATCH) ? t + (size_t)(b - BATCH) * FEAT
                                                     : v + (size_t)b * FEAT);
    uint2* dst = (uint2*)(g_emb + (size_t)b * FEAT);
    int tid = threadIdx.x;
    float4 x0 = src[tid], x1 = src[tid + 256];
    float s = x0.x * x0.x + x0.y * x0.y + x0.z * x0.z + x0.w * x0.w
            + x1.x * x1.x + x1.y * x1.y + x1.z * x1.z + x1.w * x1.w;
    s = blockReduceSum(s, sm);
    float inv = rsqrtf(s);
    __nv_bfloat162 h0 = __floats2bfloat162_rn(x0.x * inv, x0.y * inv);
    __nv_bfloat162 h1 = __floats2bfloat162_rn(x0.z * inv, x0.w * inv);
    __nv_bfloat162 h2 = __floats2bfloat162_rn(x1.x * inv, x1.y * inv);
    __nv_bfloat162 h3 = __floats2bfloat162_rn(x1.z * inv, x1.w * inv);
    uint2 o0, o1;
    o0.x = *(uint32_t*)&h0; o0.y = *(uint32_t*)&h1;
    o1.x = *(uint32_t*)&h2; o1.y = *(uint32_t*)&h3;
    dst[tid] = o0;
    dst[tid + 256] = o1;
}

// ---------------- transpose W -> bf16 g_Wt + exact norms (no atomics) -----------
__global__ void transpose_norm_kernel(const float* __restrict__ W) {
    __shared__ float tile[64][33];
    int tx = threadIdx.x, ty = threadIdx.y;
    int n = blockIdx.x * 32 + tx;
    bool nok = (n < NCLS);
    float acc4[4] = {0.f, 0.f, 0.f, 0.f};

    for (int kb = 0; kb < FEAT / 64; kb++) {
        int k0 = kb * 64;
        #pragma unroll
        for (int i = 0; i < 8; i++) {
            int k = k0 + ty + i * 8;
            tile[ty + i * 8][tx] = nok ? W[(size_t)k * NCLS + n] : 0.f;
        }
        __syncthreads();
        #pragma unroll
        for (int kk = 0; kk < 4; kk++) {
            int nl = ty + kk * 8;
            int gn = blockIdx.x * 32 + nl;
            float f0 = tile[tx * 2][nl], f1 = tile[tx * 2 + 1][nl];
            __nv_bfloat162 h = __floats2bfloat162_rn(f0, f1);
            *(__nv_bfloat162*)(g_Wt + (size_t)gn * FEAT + k0 + tx * 2) = h;
            float2 ff = __bfloat1622float2(h);
            acc4[kk] = fmaf(ff.x, ff.x, fmaf(ff.y, ff.y, acc4[kk]));
        }
        __syncthreads();
    }
    #pragma unroll
    for (int kk = 0; kk < 4; kk++) {
        float s = acc4[kk];
        #pragma unroll
        for (int o = 16; o > 0; o >>= 1) s += __shfl_xor_sync(0xffffffffu, s, o);
        if (tx == 0)
            g_invwn[blockIdx.x * 32 + ty + kk * 8] = rsqrtf(fmaxf(s, 1e-20f));
    }
}

// ---------------- mega kernel: gemm (1376) + sim (64) + lab (256) ---------------
__global__ __launch_bounds__(256, 2) void mega_kernel(const void* labels) {
    extern __shared__ float smf[];
    int bid = blockIdx.x;
    int tid = threadIdx.x;

    if (bid < NB_GEMM) {
        // ---- classifier GEMM tile + fused sumexp epilogue ----
        int colBase = (bid % CTN) * BN;
        int rowBase = (bid / CTN) * BM;
        const __nv_bfloat16* Ag = g_emb + (size_t)rowBase * FEAT;
        const __nv_bfloat16* Bg = g_Wt + (size_t)colBase * FEAT;

        float acc[4][4][4];
        #pragma unroll
        for (int m = 0; m < 4; m++)
            #pragma unroll
            for (int n = 0; n < 4; n++)
                #pragma unroll
                for (int q = 0; q < 4; q++) acc[m][n][q] = 0.f;

        gemm_mainloop_bf16(Ag, Bg, acc, smf);

        int wid = tid >> 5, lane = tid & 31;
        int wm = (wid >> 2) * 64, wn = (wid & 3) * 32;
        int lq = lane >> 2, lk = lane & 3;

        float rs[4][2];
        #pragma unroll
        for (int mf = 0; mf < 4; mf++) { rs[mf][0] = 0.f; rs[mf][1] = 0.f; }
        #pragma unroll
        for (int nf = 0; nf < 4; nf++) {
            int c = colBase + wn + nf * 8 + 2 * lk;
            float w0 = 28.f * g_invwn[c];
            float w1 = 28.f * g_invwn[c + 1];
            bool in0 = (c < NCLS), in1 = (c + 1 < NCLS);
            #pragma unroll
            for (int mf = 0; mf < 4; mf++) {
                float e0 = in0 ? __expf(fmaf(w0, acc[mf][nf][0], -28.f)) : 0.f;
                float e1 = in1 ? __expf(fmaf(w1, acc[mf][nf][1], -28.f)) : 0.f;
                float e2 = in0 ? __expf(fmaf(w0, acc[mf][nf][2], -28.f)) : 0.f;
                float e3 = in1 ? __expf(fmaf(w1, acc[mf][nf][3], -28.f)) : 0.f;
                rs[mf][0] += e0 + e1;
                rs[mf][1] += e2 + e3;
            }
        }
        #pragma unroll
        for (int mf = 0; mf < 4; mf++)
            #pragma unroll
            for (int h = 0; h < 2; h++) {
                rs[mf][h] += __shfl_xor_sync(0xffffffffu, rs[mf][h], 1);
                rs[mf][h] += __shfl_xor_sync(0xffffffffu, rs[mf][h], 2);
            }
        float* red = smf;  // 512 floats; safe after final mainloop sync
        if (lk == 0) {
            #pragma unroll
            for (int mf = 0; mf < 4; mf++)
                #pragma unroll
                for (int h = 0; h < 2; h++)
                    red[(wm + mf * 16 + lq + 8 * h) * 4 + (wid & 3)] = rs[mf][h];
        }
        __syncthreads();
        if (tid < 128) {
            float s = red[tid * 4] + red[tid * 4 + 1] + red[tid * 4 + 2] + red[tid * 4 + 3];
            g_partial[(size_t)(rowBase + tid) * CTN + (bid % CTN)] = s;
        }
    } else if (bid < NB_GEMM + NB_SIM) {
        // ---- similarity GEMM tile + fused masked softplus ----
        int i = bid - NB_GEMM;
        int colBase = (i & 7) * BN;   // textual
        int rowBase = (i >> 3) * BM;  // visual
        const __nv_bfloat16* Ag = g_emb + (size_t)rowBase * FEAT;
        const __nv_bfloat16* Bg = g_emb + (size_t)(BATCH + colBase) * FEAT;

        float acc[4][4][4];
        #pragma unroll
        for (int m = 0; m < 4; m++)
            #pragma unroll
            for (int n = 0; n < 4; n++)
                #pragma unroll
                for (int q = 0; q < 4; q++) acc[m][n][q] = 0.f;

        gemm_mainloop_bf16(Ag, Bg, acc, smf);

        int wid = tid >> 5, lane = tid & 31;
        int wm = (wid >> 2) * 64, wn = (wid & 3) * 32;
        int lq = lane >> 2, lk = lane & 3;

        int* scol = (int*)(smf + 1024);
        int* srow = (int*)(smf + 1024 + 128);
        if (tid < 128) {
            scol[tid] = get_label(labels, colBase + tid);
            srow[tid] = get_label(labels, rowBase + tid);
        }
        __syncthreads();

        float s = 0.f;
        #pragma unroll
        for (int mf = 0; mf < 4; mf++) {
            int r0 = wm + mf * 16 + lq;
            int la = srow[r0], lb = srow[r0 + 8];
            #pragma unroll
            for (int nf = 0; nf < 4; nf++) {
                int c = wn + nf * 8 + 2 * lk;
                int lc0 = scol[c], lc1 = scol[c + 1];
                float x0 = acc[mf][nf][0], x1 = acc[mf][nf][1];
                float x2 = acc[mf][nf][2], x3 = acc[mf][nf][3];
                s += softplusf((la == lc0) ? (-10.f * (x0 - 0.6f)) : (40.f * (x0 - 0.4f)));
                s += softplusf((la == lc1) ? (-10.f * (x1 - 0.6f)) : (40.f * (x1 - 0.4f)));
                s += softplusf((lb == lc0) ? (-10.f * (x2 - 0.6f)) : (40.f * (x2 - 0.4f)));
                s += softplusf((lb == lc1) ? (-10.f * (x3 - 0.6f)) : (40.f * (x3 - 0.4f)));
            }
        }
        __syncthreads();
        s = blockReduceSum(s, smf);
        if (tid == 0) g_simpart[i] = s;
    } else {
        // ---- label logits: 8 rows per block, 1 warp per row ----
        int idx = bid - (NB_GEMM + NB_SIM);      // 0..255
        int w = tid >> 5, lane = tid & 31;
        int row = idx * 8 + w;                   // 0..2047
        int lab = get_label(labels, row & (BATCH - 1));
        const uint4* e  = (const uint4*)(g_emb + (size_t)row * FEAT);
        const uint4* wv = (const uint4*)(g_Wt + (size_t)lab * FEAT);
        float s = 0.f;
        #pragma unroll
        for (int it = 0; it < 8; it++) {
            uint4 ue = e[lane + it * 32];
            uint4 uw = wv[lane + it * 32];
            const __nv_bfloat162* he = (const __nv_bfloat162*)&ue;
            const __nv_bfloat162* hw = (const __nv_bfloat162*)&uw;
            #pragma unroll
            for (int q = 0; q < 4; q++) {
                float2 fe = __bfloat1622float2(he[q]);
                float2 fw = __bfloat1622float2(hw[q]);
                s = fmaf(fe.x, fw.x, s);
                s = fmaf(fe.y, fw.y, s);
            }
        }
        #pragma unroll
        for (int o = 16; o > 0; o >>= 1) s += __shfl_xor_sync(0xffffffffu, s, o);
        if (lane == 0) g_lab[row] = 28.f * s * g_invwn[lab];
    }
}

// ---------------- finalize ------------------------------------------------------
__global__ void finalize_kernel(float* __restrict__ out) {
    __shared__ float sm[256];
    int tid = threadIdx.x;
    float ce = 0.f;
    for (int r = tid; r < 2 * BATCH; r += 256) {
        float s = 0.f;
        const float* p = &g_partial[(size_t)r * CTN];
        for (int c = 0; c < CTN; c++) s += p[c];
        ce += 28.f + logf(s) - g_lab[r];
    }
    ce = blockReduceSum(ce, sm);
    float simv = (tid < NB_SIM) ? g_simpart[tid] : 0.f;
    simv = blockReduceSum(simv, sm);
    if (tid == 0) {
        out[0] = ce / (float)BATCH;
        out[1] = 2.f * simv / (float)BATCH;
    }
}

// ---------------- launch --------------------------------------------------------
extern "C" void kernel_launch(void* const* d_in, const int* in_sizes, int n_in,
                              void* d_out, int out_size) {
    const float* v = (const float*)d_in[0];
    const float* t = (const float*)d_in[1];
    const void*  labels = d_in[2];
    const float* W = (const float*)d_in[3];
    float* out = (float*)d_out;

    cudaFuncSetAttribute(mega_kernel, cudaFuncAttributeMaxDynamicSharedMemorySize,
                         SMEM_ALLOC);

    detect_labels_kernel<<<1, 32>>>(labels);
    prep_kernel<<<2 * BATCH, 256>>>(v, t);
    transpose_norm_kernel<<<NCLSP / 32, dim3(32, 8)>>>(W);
    mega_kernel<<<NB_GEMM + NB_SIM + NB_LAB, 256, SMEM_ALLOC>>>(labels);
    finalize_kernel<<<1, 256>>>(out);
}

// round 16
// speedup vs baseline: 7.6860x; 1.0693x over previous
#include <cuda_runtime.h>
#include <cuda_bf16.h>
#include <math.h>
#include <stdint.h>

#define BATCH 1024
#define FEAT  2048
#define NCLS  11003
#define NCLSP 11008
#define CTN   86            // ceil(11003/128)
#define BM 128
#define BN 128
#define BK 64               // bf16 elements per chunk
#define NITER (FEAT/BK)     // 32
#define PITCH 144           // bytes per smem row (128 data + 16 pad)
#define A_BYTES (BM*PITCH)              // 18432
#define B_BYTES (BN*PITCH)              // 18432
#define STAGE_BYTES (A_BYTES + B_BYTES) // 36864
#define SMEM_ALLOC (3*STAGE_BYTES)      // 110592 -> 2 CTAs/SM

#define NB_GEMM 1376         // 16 row-tiles * 86 col-tiles
#define NB_SIM  64           // 8 x 8 tiles of 128
#define NB_LAB  256          // 2048 rows / 8 per block
#define NB_PREP 2048
#define NB_TRANS 344         // NCLSP/32

// ---------------- scratch -----------------------------------------------------
__device__ __nv_bfloat16 g_emb[2 * BATCH * FEAT];       // normalized v,t rows (bf16)
__device__ __nv_bfloat16 g_Wt[(size_t)NCLSP * FEAT];    // raw W^T (bf16, padded 0)
__device__ float g_invwn[NCLSP];
__device__ float g_partial[2 * BATCH * CTN];
__device__ float g_lab[2 * BATCH];
__device__ float g_rowce[2 * BATCH];
__device__ float g_simpart[NB_SIM];
__device__ int   g_lab32;

// ---------------- helpers ------------------------------------------------------
static __device__ __forceinline__ uint32_t smem_u32(const void* p) {
    uint32_t a;
    asm("{ .reg .u64 t; cvta.to.shared.u64 t, %1; cvt.u32.u64 %0, t; }"
        : "=r"(a) : "l"(p));
    return a;
}
static __device__ __forceinline__ void cp16(uint32_t dst, const void* src) {
    asm volatile("cp.async.cg.shared.global [%0], [%1], 16;"
                 :: "r"(dst), "l"(src) : "memory");
}
__device__ __forceinline__ float blockReduceSum(float v, float* sm) {
    int tid = threadIdx.x;
    sm[tid] = v;
    __syncthreads();
    for (int s = blockDim.x >> 1; s > 0; s >>= 1) {
        if (tid < s) sm[tid] += sm[tid + s];
        __syncthreads();
    }
    float r = sm[0];
    __syncthreads();
    return r;
}
__device__ __forceinline__ int get_label(const void* labels, int i) {
    if (g_lab32) return ((const int*)labels)[i];
    return (int)(((const long long*)labels)[i]);
}
__device__ __forceinline__ float softplusf(float x) {
    return fmaxf(x, 0.f) + log1pf(__expf(-fabsf(x)));
}

#define LDSM4(r0, r1, r2, r3, addr) \
    asm volatile("ldmatrix.sync.aligned.m8n8.x4.shared.b16 {%0,%1,%2,%3}, [%4];" \
                 : "=r"(r0), "=r"(r1), "=r"(r2), "=r"(r3) : "r"(addr))

#define MMA_BF16(d, a0, a1, a2, a3, b0, b1) \
    asm volatile("mma.sync.aligned.m16n8k16.row.col.f32.bf16.bf16.f32 " \
                 "{%0,%1,%2,%3}, {%4,%5,%6,%7}, {%8,%9}, {%0,%1,%2,%3};" \
                 : "+f"(d[0]), "+f"(d[1]), "+f"(d[2]), "+f"(d[3]) \
                 : "r"(a0), "r"(a1), "r"(a2), "r"(a3), "r"(b0), "r"(b1))

// C[128x128] += A[128x2048] @ B[128x2048]^T, bf16 operands, fp32 accum.
// 8 warps (2m x 4n), warp tile 64x32. 3-stage cp.async pipeline, one sync/chunk.
static __device__ __forceinline__ void gemm_mainloop_bf16(
        const __nv_bfloat16* __restrict__ Ag,
        const __nv_bfloat16* __restrict__ Bg,
        float (&acc)[4][4][4], float* smf) {
    const int tid = threadIdx.x;
    const int wid = tid >> 5, lane = tid & 31;
    const int wm = (wid >> 2) * 64, wn = (wid & 3) * 32;
    uint32_t sb = smem_u32(smf);

    int aSm[4], aG[4];
    #pragma unroll
    for (int i = 0; i < 4; i++) {
        int f = tid + i * 256, r = f >> 3, c = f & 7;
        aSm[i] = r * PITCH + c * 16;
        aG[i]  = r * FEAT + c * 8;
    }
    uint32_t stBase[3] = { sb, sb + STAGE_BYTES, sb + 2u * STAGE_BYTES };

    uint32_t aLd = (uint32_t)((wm + (lane & 15)) * PITCH + ((lane >> 4) & 1) * 16);
    uint32_t bLd = (uint32_t)(A_BYTES +
                   (wn + (lane & 7) + ((lane >> 4) & 1) * 8) * PITCH +
                   ((lane >> 3) & 1) * 16);

    #pragma unroll
    for (int st = 0; st < 2; st++) {
        int k0 = st * BK;
        #pragma unroll
        for (int i = 0; i < 4; i++) cp16(stBase[st] + aSm[i], Ag + aG[i] + k0);
        #pragma unroll
        for (int i = 0; i < 4; i++) cp16(stBase[st] + A_BYTES + aSm[i], Bg + aG[i] + k0);
        asm volatile("cp.async.commit_group;" ::: "memory");
    }

    for (int s = 0; s < NITER; s++) {
        asm volatile("cp.async.wait_group 1;" ::: "memory");
        __syncthreads();
        if (s + 2 < NITER) {
            int k0 = (s + 2) * BK;
            uint32_t base = stBase[(s + 2) % 3];
            #pragma unroll
            for (int i = 0; i < 4; i++) cp16(base + aSm[i], Ag + aG[i] + k0);
            #pragma unroll
            for (int i = 0; i < 4; i++) cp16(base + A_BYTES + aSm[i], Bg + aG[i] + k0);
        }
        asm volatile("cp.async.commit_group;" ::: "memory");

        uint32_t base = stBase[s % 3];
        #pragma unroll
        for (int kk = 0; kk < 4; kk++) {
            uint32_t b[8];
            LDSM4(b[0], b[1], b[2], b[3], base + bLd + kk * 32);
            LDSM4(b[4], b[5], b[6], b[7], base + bLd + 16 * PITCH + kk * 32);
            #pragma unroll
            for (int mf = 0; mf < 4; mf++) {
                uint32_t a0, a1, a2, a3;
                LDSM4(a0, a1, a2, a3, base + aLd + mf * (16 * PITCH) + kk * 32);
                MMA_BF16(acc[mf][0], a0, a1, a2, a3, b[0], b[1]);
                MMA_BF16(acc[mf][1], a0, a1, a2, a3, b[2], b[3]);
                MMA_BF16(acc[mf][2], a0, a1, a2, a3, b[4], b[5]);
                MMA_BF16(acc[mf][3], a0, a1, a2, a3, b[6], b[7]);
            }
        }
    }
    __syncthreads();   // smem reusable by epilogue after this
}

// ---------------- label dtype detection ---------------------------------------
__global__ void detect_labels_kernel(const void* labels) {
    if (threadIdx.x == 0 && blockIdx.x == 0) {
        const long long* p = (const long long*)labels;
        int is32 = 0;
        for (int i = 0; i < 16; i++) {
            long long v = p[i];
            if (v < 0 || v >= (long long)NCLS) { is32 = 1; break; }
        }
        g_lab32 = is32;
    }
}

// ---------------- prepare: row-normalize embeds (2048) + transpose W (344) ------
__global__ void prepare_kernel(const float* __restrict__ v,
                               const float* __restrict__ t,
                               const float* __restrict__ W) {
    __shared__ float shmem[64 * 33];   // transpose tile; prep uses first 256
    int bid = blockIdx.x;
    int tid = threadIdx.x;

    if (bid < NB_PREP) {
        // ---- L2-normalize one embedding row -> bf16 ----
        int b = bid;
        const float4* src = (const float4*)((b >= BATCH)
                              ? t + (size_t)(b - BATCH) * FEAT
                              : v + (size_t)b * FEAT);
        uint2* dst = (uint2*)(g_emb + (size_t)b * FEAT);
        float4 x0 = src[tid], x1 = src[tid + 256];
        float s = x0.x * x0.x + x0.y * x0.y + x0.z * x0.z + x0.w * x0.w
                + x1.x * x1.x + x1.y * x1.y + x1.z * x1.z + x1.w * x1.w;
        s = blockReduceSum(s, shmem);
        float inv = rsqrtf(s);
        __nv_bfloat162 h0 = __floats2bfloat162_rn(x0.x * inv, x0.y * inv);
        __nv_bfloat162 h1 = __floats2bfloat162_rn(x0.z * inv, x0.w * inv);
        __nv_bfloat162 h2 = __floats2bfloat162_rn(x1.x * inv, x1.y * inv);
        __nv_bfloat162 h3 = __floats2bfloat162_rn(x1.z * inv, x1.w * inv);
        uint2 o0, o1;
        o0.x = *(uint32_t*)&h0; o0.y = *(uint32_t*)&h1;
        o1.x = *(uint32_t*)&h2; o1.y = *(uint32_t*)&h3;
        dst[tid] = o0;
        dst[tid + 256] = o1;
    } else {
        // ---- transpose one 32-column strip of W -> bf16 g_Wt, exact norms ----
        float (*tile)[33] = (float(*)[33])shmem;
        int strip = bid - NB_PREP;
        int tx = tid & 31, ty = tid >> 5;     // (32, 8)
        int n = strip * 32 + tx;
        bool nok = (n < NCLS);
        float acc4[4] = {0.f, 0.f, 0.f, 0.f};

        for (int kb = 0; kb < FEAT / 64; kb++) {
            int k0 = kb * 64;
            #pragma unroll
            for (int i = 0; i < 8; i++) {
                int k = k0 + ty + i * 8;
                tile[ty + i * 8][tx] = nok ? W[(size_t)k * NCLS + n] : 0.f;
            }
            __syncthreads();
            #pragma unroll
            for (int kk = 0; kk < 4; kk++) {
                int nl = ty + kk * 8;
                int gn = strip * 32 + nl;
                float f0 = tile[tx * 2][nl], f1 = tile[tx * 2 + 1][nl];
                __nv_bfloat162 h = __floats2bfloat162_rn(f0, f1);
                *(__nv_bfloat162*)(g_Wt + (size_t)gn * FEAT + k0 + tx * 2) = h;
                float2 ff = __bfloat1622float2(h);
                acc4[kk] = fmaf(ff.x, ff.x, fmaf(ff.y, ff.y, acc4[kk]));
            }
            __syncthreads();
        }
        #pragma unroll
        for (int kk = 0; kk < 4; kk++) {
            float s = acc4[kk];
            #pragma unroll
            for (int o = 16; o > 0; o >>= 1) s += __shfl_xor_sync(0xffffffffu, s, o);
            if (tx == 0)
                g_invwn[strip * 32 + ty + kk * 8] = rsqrtf(fmaxf(s, 1e-20f));
        }
    }
}

// ---------------- mega kernel: gemm (1376) + sim (64) + lab (256) ---------------
__global__ __launch_bounds__(256, 2) void mega_kernel(const void* labels) {
    extern __shared__ float smf[];
    int bid = blockIdx.x;
    int tid = threadIdx.x;

    if (bid < NB_GEMM) {
        int colBase = (bid % CTN) * BN;
        int rowBase = (bid / CTN) * BM;
        const __nv_bfloat16* Ag = g_emb + (size_t)rowBase * FEAT;
        const __nv_bfloat16* Bg = g_Wt + (size_t)colBase * FEAT;

        float acc[4][4][4];
        #pragma unroll
        for (int m = 0; m < 4; m++)
            #pragma unroll
            for (int n = 0; n < 4; n++)
                #pragma unroll
                for (int q = 0; q < 4; q++) acc[m][n][q] = 0.f;

        gemm_mainloop_bf16(Ag, Bg, acc, smf);

        int wid = tid >> 5, lane = tid & 31;
        int wm = (wid >> 2) * 64, wn = (wid & 3) * 32;
        int lq = lane >> 2, lk = lane & 3;

        float rs[4][2];
        #pragma unroll
        for (int mf = 0; mf < 4; mf++) { rs[mf][0] = 0.f; rs[mf][1] = 0.f; }
        #pragma unroll
        for (int nf = 0; nf < 4; nf++) {
            int c = colBase + wn + nf * 8 + 2 * lk;
            float w0 = 28.f * g_invwn[c];
            float w1 = 28.f * g_invwn[c + 1];
            bool in0 = (c < NCLS), in1 = (c + 1 < NCLS);
            #pragma unroll
            for (int mf = 0; mf < 4; mf++) {
                float e0 = in0 ? __expf(fmaf(w0, acc[mf][nf][0], -28.f)) : 0.f;
                float e1 = in1 ? __expf(fmaf(w1, acc[mf][nf][1], -28.f)) : 0.f;
                float e2 = in0 ? __expf(fmaf(w0, acc[mf][nf][2], -28.f)) : 0.f;
                float e3 = in1 ? __expf(fmaf(w1, acc[mf][nf][3], -28.f)) : 0.f;
                rs[mf][0] += e0 + e1;
                rs[mf][1] += e2 + e3;
            }
        }
        #pragma unroll
        for (int mf = 0; mf < 4; mf++)
            #pragma unroll
            for (int h = 0; h < 2; h++) {
                rs[mf][h] += __shfl_xor_sync(0xffffffffu, rs[mf][h], 1);
                rs[mf][h] += __shfl_xor_sync(0xffffffffu, rs[mf][h], 2);
            }
        float* red = smf;
        if (lk == 0) {
            #pragma unroll
            for (int mf = 0; mf < 4; mf++)
                #pragma unroll
                for (int h = 0; h < 2; h++)
                    red[(wm + mf * 16 + lq + 8 * h) * 4 + (wid & 3)] = rs[mf][h];
        }
        __syncthreads();
        if (tid < 128) {
            float s = red[tid * 4] + red[tid * 4 + 1] + red[tid * 4 + 2] + red[tid * 4 + 3];
            g_partial[(size_t)(rowBase + tid) * CTN + (bid % CTN)] = s;
        }
    } else if (bid < NB_GEMM + NB_SIM) {
        int i = bid - NB_GEMM;
        int colBase = (i & 7) * BN;   // textual
        int rowBase = (i >> 3) * BM;  // visual
        const __nv_bfloat16* Ag = g_emb + (size_t)rowBase * FEAT;
        const __nv_bfloat16* Bg = g_emb + (size_t)(BATCH + colBase) * FEAT;

        float acc[4][4][4];
        #pragma unroll
        for (int m = 0; m < 4; m++)
            #pragma unroll
            for (int n = 0; n < 4; n++)
                #pragma unroll
                for (int q = 0; q < 4; q++) acc[m][n][q] = 0.f;

        gemm_mainloop_bf16(Ag, Bg, acc, smf);

        int wid = tid >> 5, lane = tid & 31;
        int wm = (wid >> 2) * 64, wn = (wid & 3) * 32;
        int lq = lane >> 2, lk = lane & 3;

        int* scol = (int*)(smf + 1024);
        int* srow = (int*)(smf + 1024 + 128);
        if (tid < 128) {
            scol[tid] = get_label(labels, colBase + tid);
            srow[tid] = get_label(labels, rowBase + tid);
        }
        __syncthreads();

        float s = 0.f;
        #pragma unroll
        for (int mf = 0; mf < 4; mf++) {
            int r0 = wm + mf * 16 + lq;
            int la = srow[r0], lb = srow[r0 + 8];
            #pragma unroll
            for (int nf = 0; nf < 4; nf++) {
                int c = wn + nf * 8 + 2 * lk;
                int lc0 = scol[c], lc1 = scol[c + 1];
                float x0 = acc[mf][nf][0], x1 = acc[mf][nf][1];
                float x2 = acc[mf][nf][2], x3 = acc[mf][nf][3];
                s += softplusf((la == lc0) ? (-10.f * (x0 - 0.6f)) : (40.f * (x0 - 0.4f)));
                s += softplusf((la == lc1) ? (-10.f * (x1 - 0.6f)) : (40.f * (x1 - 0.4f)));
                s += softplusf((lb == lc0) ? (-10.f * (x2 - 0.6f)) : (40.f * (x2 - 0.4f)));
                s += softplusf((lb == lc1) ? (-10.f * (x3 - 0.6f)) : (40.f * (x3 - 0.4f)));
            }
        }
        __syncthreads();
        s = blockReduceSum(s, smf);
        if (tid == 0) g_simpart[i] = s;
    } else {
        int idx = bid - (NB_GEMM + NB_SIM);      // 0..255
        int w = tid >> 5, lane = tid & 31;
        int row = idx * 8 + w;                   // 0..2047
        int lab = get_label(labels, row & (BATCH - 1));
        const uint4* e  = (const uint4*)(g_emb + (size_t)row * FEAT);
        const uint4* wv = (const uint4*)(g_Wt + (size_t)lab * FEAT);
        float s = 0.f;
        #pragma unroll
        for (int it = 0; it < 8; it++) {
            uint4 ue = e[lane + it * 32];
            uint4 uw = wv[lane + it * 32];
            const __nv_bfloat162* he = (const __nv_bfloat162*)&ue;
            const __nv_bfloat162* hw = (const __nv_bfloat162*)&uw;
            #pragma unroll
            for (int q = 0; q < 4; q++) {
                float2 fe = __bfloat1622float2(he[q]);
                float2 fw = __bfloat1622float2(hw[q]);
                s = fmaf(fe.x, fw.x, s);
                s = fmaf(fe.y, fw.y, s);
            }
        }
        #pragma unroll
        for (int o = 16; o > 0; o >>= 1) s += __shfl_xor_sync(0xffffffffu, s, o);
        if (lane == 0) g_lab[row] = 28.f * s * g_invwn[lab];
    }
}

// ---------------- per-row CE term (parallel) ------------------------------------
// 256 blocks x 8 warps, one warp per row: ce_r = 28 + log(sum partial) - lab_r
__global__ void rowce_kernel() {
    int w = threadIdx.x >> 5, lane = threadIdx.x & 31;
    int row = blockIdx.x * 8 + w;                 // 0..2047
    const float* p = &g_partial[(size_t)row * CTN];
    float s = 0.f;
    if (lane < CTN) s += p[lane];
    s += p[lane + 32];                            // 32..63  (<86 always)
    if (lane + 64 < CTN) s += p[lane + 64];
    #pragma unroll
    for (int o = 16; o > 0; o >>= 1) s += __shfl_xor_sync(0xffffffffu, s, o);
    if (lane == 0) g_rowce[row] = 28.f + logf(s) - g_lab[row];
}

// ---------------- finalize ------------------------------------------------------
__global__ void finalize_kernel(float* __restrict__ out) {
    __shared__ float sm[256];
    int tid = threadIdx.x;
    float ce = 0.f;
    #pragma unroll
    for (int i = 0; i < 8; i++) ce += g_rowce[tid + i * 256];
    ce = blockReduceSum(ce, sm);
    float simv = (tid < NB_SIM) ? g_simpart[tid] : 0.f;
    simv = blockReduceSum(simv, sm);
    if (tid == 0) {
        out[0] = ce / (float)BATCH;
        out[1] = 2.f * simv / (float)BATCH;
    }
}

// ---------------- launch --------------------------------------------------------
extern "C" void kernel_launch(void* const* d_in, const int* in_sizes, int n_in,
                              void* d_out, int out_size) {
    const float* v = (const float*)d_in[0];
    const float* t = (const float*)d_in[1];
    const void*  labels = d_in[2];
    const float* W = (const float*)d_in[3];
    float* out = (float*)d_out;

    cudaFuncSetAttribute(mega_kernel, cudaFuncAttributeMaxDynamicSharedMemorySize,
                         SMEM_ALLOC);

    detect_labels_kernel<<<1, 32>>>(labels);
    prepare_kernel<<<NB_PREP + NB_TRANS, 256>>>(v, t, W);
    mega_kernel<<<NB_GEMM + NB_SIM + NB_LAB, 256, SMEM_ALLOC>>>(labels);
    rowce_kernel<<<256, 256>>>();
    finalize_kernel<<<1, 256>>>(out);
}